// round 4
// baseline (speedup 1.0000x reference)
#include <cuda_runtime.h>
#include <math.h>

#define N_      4
#define C_      21
#define H_      512
#define W_      512
#define HW      (H_*W_)
#define PH      171
#define PP      (PH*PH)      // 29241
#define NH      169
#define M_      (NH*NH)      // 28561
#define NC      (N_*C_)      // 84
#define ALPHA   5e-4
#define CLIPMIN 1e-6f
#define SPLIT   8
#define CHUNK   ((M_ + SPLIT - 1) / SPLIT)   // 3571
#define GRAMSZ  (NC*3*81)
#define FULLM   0xffffffffu

// ------------------------- device scratch ----------------------------------
__device__ float  g_la[NC*PP];
__device__ float  g_pr[NC*PP];
__device__ double g_gram[GRAMSZ];
__device__ double g_bce;
__device__ double g_valid;
__device__ double g_rmi;
__device__ int    g_lab64;

// ------------------------- kernel 0: zero grams + dtype sniff --------------
__global__ void k_init(const void* lab) {
    const int i = blockIdx.x * blockDim.x + threadIdx.x;
    if (i < GRAMSZ) g_gram[i] = 0.0;
    if (i == 0) {
        const int* p = (const int*)lab;
        bool is64 = true;
        #pragma unroll 1
        for (int k = 0; k < 64; k++)
            if (p[2*k + 1] != 0) { is64 = false; break; }
        g_lab64 = is64 ? 1 : 0;
        g_bce = 0.0; g_valid = 0.0; g_rmi = 0.0;
    }
}

// ------------------------- kernel 1: fused max-pool + BCE (R1 version) -----
__global__ void __launch_bounds__(128)
k_pool_bce(const float* __restrict__ logits, const void* __restrict__ labv) {
    const int p = blockIdx.x * blockDim.x + threadIdx.x;
    const int n = blockIdx.y;

    float bce_acc = 0.f;
    int   valid   = 0;

    if (p < PP) {
        const int i  = p / PH, j = p - i * PH;
        const int y0 = 3*i - 1, x0 = 3*j - 1;

        const bool is64 = (g_lab64 != 0);
        const long long* L64 = (const long long*)labv;
        const int*       L32 = (const int*)labv;

        int offs[9];
        int labs[9];
        int cnt = 0;
        #pragma unroll
        for (int dy = 0; dy < 3; dy++) {
            #pragma unroll
            for (int dx = 0; dx < 3; dx++) {
                const int y = y0 + dy, x = x0 + dx;
                if (y >= 0 && y < H_ && x >= 0 && x < W_) {
                    const int idx = (n*H_ + y)*W_ + x;
                    const int lv  = is64 ? (int)L64[idx] : L32[idx];
                    offs[cnt] = y*W_ + x;
                    labs[cnt] = lv;
                    cnt++;
                }
            }
        }
        #pragma unroll 9
        for (int k = 0; k < 9; k++)
            if (k < cnt && labs[k] >= 0 && labs[k] < C_) valid++;

        const int ncbase = n * C_;
        #pragma unroll 1
        for (int c = 0; c < C_; c++) {
            const float* __restrict__ base = logits + (size_t)(ncbase + c) * HW;
            float maxp = 0.f;     // max over (mask ? sigmoid : 0)
            int   anyl = 0;
            #pragma unroll 9
            for (int k = 0; k < 9; k++) {
                if (k >= cnt) break;
                const int   lv = labs[k];
                const bool  m  = (lv >= 0 && lv < C_);
                const float xv = base[offs[k]];
                const float t  = __expf(-fabsf(xv));
                const float u  = __fdividef(1.f, 1.f + t);
                const float sg = (xv >= 0.f) ? u : t * u;
                const float sp = fmaxf(xv, 0.f) + __logf(1.f + t);
                const float yv = (m && lv == c) ? 1.f : 0.f;
                if (m) bce_acc += sp - yv * xv;
                maxp = fmaxf(maxp, m ? sg : 0.f);
                anyl |= (m && lv == c);
            }
            g_pr[(ncbase + c)*PP + p] = maxp + CLIPMIN;
            g_la[(ncbase + c)*PP + p] = anyl ? 1.f : 0.f;
        }
    }

    double b = (double)bce_acc, v = (double)valid;
    #pragma unroll
    for (int o = 16; o > 0; o >>= 1) {
        b += __shfl_down_sync(FULLM, b, o);
        v += __shfl_down_sync(FULLM, v, o);
    }
    __shared__ double sb[4], sv[4];
    const int lane = threadIdx.x & 31, wid = threadIdx.x >> 5;
    if (lane == 0) { sb[wid] = b; sv[wid] = v; }
    __syncthreads();
    if (threadIdx.x == 0) {
        atomicAdd(&g_bce,   sb[0] + sb[1] + sb[2] + sb[3]);
        atomicAdd(&g_valid, sv[0] + sv[1] + sv[2] + sv[3]);
    }
}

// ------------------------- kernel 2: 9x9 Grams (3 kernels, M-split) --------
// V=0: la Gram (45 tri + 9 sums); V=1: pr Gram; V=2: la x pr (81 full).
template<int V>
__global__ void __launch_bounds__(256)
k_gram() {
    constexpr int NACC = (V == 2) ? 81 : 54;
    __shared__ double smem[8][NACC];

    const int nc = blockIdx.x;
    const int m0 = blockIdx.y * CHUNK;
    const int m1 = (m0 + CHUNK < M_) ? m0 + CHUNK : M_;
    const float* __restrict__ A = ((V == 1) ? g_pr : g_la) + (size_t)nc * PP;
    const float* __restrict__ B = g_pr + (size_t)nc * PP;

    float acc[NACC];
    #pragma unroll
    for (int k = 0; k < NACC; k++) acc[k] = 0.f;

    for (int m = m0 + threadIdx.x; m < m1; m += 256) {
        const int i = m / NH, j = m - i * NH;
        const float* pa = A + i*PH + j;
        float a[9];
        #pragma unroll
        for (int d = 0; d < 9; d++) a[d] = pa[(d/3)*PH + (d%3)];
        if (V == 2) {
            const float* pb = B + i*PH + j;
            float bb[9];
            #pragma unroll
            for (int d = 0; d < 9; d++) bb[d] = pb[(d/3)*PH + (d%3)];
            #pragma unroll
            for (int d = 0; d < 9; d++)
                #pragma unroll
                for (int e = 0; e < 9; e++)
                    acc[d*9 + e] += a[d] * bb[e];
        } else {
            int k = 0;
            #pragma unroll
            for (int d = 0; d < 9; d++)
                #pragma unroll
                for (int e = d; e < 9; e++)
                    acc[k++] += a[d] * a[e];
            #pragma unroll
            for (int d = 0; d < 9; d++) acc[45 + d] += a[d];
        }
    }

    // fully-unrolled warp reduce (compile-time indices -> registers)
    const int lane = threadIdx.x & 31, wid = threadIdx.x >> 5;
    #pragma unroll
    for (int k = 0; k < NACC; k++) {
        double x = (double)acc[k];
        #pragma unroll
        for (int o = 16; o > 0; o >>= 1) x += __shfl_down_sync(FULLM, x, o);
        if (lane == 0) smem[wid][k] = x;
    }
    __syncthreads();
    double* out = g_gram + (size_t)(nc*3 + V) * 81;
    for (int k = threadIdx.x; k < NACC; k += 256) {
        double s = 0.0;
        #pragma unroll
        for (int w = 0; w < 8; w++) s += smem[w][k];
        atomicAdd(&out[k], s);
    }
}

// ------------------------- kernel 3: warp-parallel linear algebra ----------
__global__ void __launch_bounds__(32)
k_finalize() {
    const int nc = blockIdx.x;
    const int d  = threadIdx.x;
    const int dd = (d < 9) ? d : 0;

    const double* __restrict__ G0 = g_gram + (size_t)(nc*3 + 0)*81;
    const double* __restrict__ G1 = g_gram + (size_t)(nc*3 + 1)*81;
    const double* __restrict__ G2 = g_gram + (size_t)(nc*3 + 2)*81;

    const double invM = 1.0 / (double)M_;
    const double sla_d = G0[45 + dd], spr_d = G1[45 + dd];

    double Cr[9], Pr[9], Br[9];
    #pragma unroll
    for (int e = 0; e < 9; e++) {
        const int lo = (dd < e) ? dd : e;
        const int hi = (dd < e) ? e : dd;
        const int tri = lo*9 - (lo*(lo-1))/2 + (hi - lo);
        const double sla_e = G0[45 + e], spr_e = G1[45 + e];
        Cr[e] = G0[tri] - sla_d*sla_e*invM + ((e == dd) ? ALPHA : 0.0);
        Pr[e] = G1[tri] - spr_d*spr_e*invM + ((e == dd) ? ALPHA : 0.0);
        Br[e] = G2[dd*9 + e] - sla_d*spr_e*invM;
    }

    // Cholesky of P: lane d ends with Lr[k] = L[d][k]
    double Lr[9];
    #pragma unroll
    for (int k = 0; k < 9; k++) {
        const double pkk = __shfl_sync(FULLM, Pr[k], k);
        const double lkk = sqrt(fmax(pkk, 1e-300));
        const double ldk = Pr[k] * (1.0 / lkk);
        Lr[k] = ldk;
        #pragma unroll
        for (int j = 0; j < 9; j++)
            if (j > k) Pr[j] -= ldk * __shfl_sync(FULLM, ldk, j);
    }

    // W = B L^{-T}
    double Wr[9];
    #pragma unroll
    for (int e = 0; e < 9; e++) {
        double s = Br[e];
        #pragma unroll
        for (int k = 0; k < 9; k++)
            if (k < e) s -= Wr[k] * __shfl_sync(FULLM, Lr[k], e);
        const double lee = __shfl_sync(FULLM, Lr[e], e);
        Wr[e] = s * (1.0 / lee);
    }

    // A2 = Cla + alpha I - W W^T
    #pragma unroll
    for (int e = 0; e < 9; e++) {
        double s = 0.0;
        #pragma unroll
        for (int k = 0; k < 9; k++)
            s += Wr[k] * __shfl_sync(FULLM, Wr[k], e);
        Cr[e] -= s;
    }

    // Cholesky of A2; sum log(diag + 1e-8)
    double lsum = 0.0;
    #pragma unroll
    for (int k = 0; k < 9; k++) {
        const double akk = __shfl_sync(FULLM, Cr[k], k);
        const double lkk = sqrt(fmax(akk, 1e-300));
        lsum += log(lkk + 1e-8);
        const double ldk = Cr[k] * (1.0 / lkk);
        #pragma unroll
        for (int j = 0; j < 9; j++)
            if (j > k) Cr[j] -= ldk * __shfl_sync(FULLM, ldk, j);
    }

    if (d == 0) atomicAdd(&g_rmi, lsum);
}

// ------------------------- kernel 4: combine --------------------------------
__global__ void k_out(float* __restrict__ outp) {
    const double rmi_total = g_rmi / (double)(N_ * 9);
    const double bce_loss  = g_bce / (g_valid + 1.0);
    outp[0] = (float)(0.5 * bce_loss + 0.5 * rmi_total);
}

// ------------------------- launch ------------------------------------------
extern "C" void kernel_launch(void* const* d_in, const int* in_sizes, int n_in,
                              void* d_out, int out_size) {
    const float* logits = (const float*)d_in[0];
    const void*  labels = d_in[1];

    k_init<<<(GRAMSZ + 255) / 256, 256>>>(labels);
    dim3 g1((PP + 127) / 128, N_);
    k_pool_bce<<<g1, 128>>>(logits, labels);
    dim3 g2(NC, SPLIT);
    k_gram<0><<<g2, 256>>>();
    k_gram<1><<<g2, 256>>>();
    k_gram<2><<<g2, 256>>>();
    k_finalize<<<NC, 32>>>();
    k_out<<<1, 1>>>((float*)d_out);
}

// round 5
// speedup vs baseline: 2.6149x; 2.6149x over previous
#include <cuda_runtime.h>
#include <math.h>

#define N_      4
#define C_      21
#define H_      512
#define W_      512
#define HW      (H_*W_)
#define PH      171
#define PP      (PH*PH)      // 29241
#define NH      169
#define M_      (NH*NH)      // 28561
#define NC      (N_*C_)      // 84
#define ALPHA   5e-4
#define CLIPMIN 1e-6f
#define RSPLIT  8
#define ROWCH   ((NH + RSPLIT - 1) / RSPLIT)   // 22
#define GRAMSZ  (NC*3*81)
#define FULLM   0xffffffffu

// ------------------------- device scratch ----------------------------------
__device__ float  g_la[NC*PP];
__device__ float  g_pr[NC*PP];
__device__ double g_gram[GRAMSZ];
__device__ double g_bce;
__device__ double g_valid;
__device__ double g_rmi;
__device__ int    g_lab64;

// ------------------------- kernel 0: zero grams + dtype sniff --------------
__global__ void k_init(const void* lab) {
    const int i = blockIdx.x * blockDim.x + threadIdx.x;
    if (i < GRAMSZ) g_gram[i] = 0.0;
    if (i == 0) {
        const int* p = (const int*)lab;
        bool is64 = true;
        #pragma unroll 1
        for (int k = 0; k < 64; k++)
            if (p[2*k + 1] != 0) { is64 = false; break; }
        g_lab64 = is64 ? 1 : 0;
        g_bce = 0.0; g_valid = 0.0; g_rmi = 0.0;
    }
}

// ------------------------- kernel 1: fused max-pool + BCE (R1 version) -----
__global__ void __launch_bounds__(128)
k_pool_bce(const float* __restrict__ logits, const void* __restrict__ labv) {
    const int p = blockIdx.x * blockDim.x + threadIdx.x;
    const int n = blockIdx.y;

    float bce_acc = 0.f;
    int   valid   = 0;

    if (p < PP) {
        const int i  = p / PH, j = p - i * PH;
        const int y0 = 3*i - 1, x0 = 3*j - 1;

        const bool is64 = (g_lab64 != 0);
        const long long* L64 = (const long long*)labv;
        const int*       L32 = (const int*)labv;

        int offs[9];
        int labs[9];
        int cnt = 0;
        #pragma unroll
        for (int dy = 0; dy < 3; dy++) {
            #pragma unroll
            for (int dx = 0; dx < 3; dx++) {
                const int y = y0 + dy, x = x0 + dx;
                if (y >= 0 && y < H_ && x >= 0 && x < W_) {
                    const int idx = (n*H_ + y)*W_ + x;
                    const int lv  = is64 ? (int)L64[idx] : L32[idx];
                    offs[cnt] = y*W_ + x;
                    labs[cnt] = lv;
                    cnt++;
                }
            }
        }
        #pragma unroll 9
        for (int k = 0; k < 9; k++)
            if (k < cnt && labs[k] >= 0 && labs[k] < C_) valid++;

        const int ncbase = n * C_;
        #pragma unroll 1
        for (int c = 0; c < C_; c++) {
            const float* __restrict__ base = logits + (size_t)(ncbase + c) * HW;
            float maxp = 0.f;
            int   anyl = 0;
            #pragma unroll 9
            for (int k = 0; k < 9; k++) {
                if (k >= cnt) break;
                const int   lv = labs[k];
                const bool  m  = (lv >= 0 && lv < C_);
                const float xv = base[offs[k]];
                const float t  = __expf(-fabsf(xv));
                const float u  = __fdividef(1.f, 1.f + t);
                const float sg = (xv >= 0.f) ? u : t * u;
                const float sp = fmaxf(xv, 0.f) + __logf(1.f + t);
                const float yv = (m && lv == c) ? 1.f : 0.f;
                if (m) bce_acc += sp - yv * xv;
                maxp = fmaxf(maxp, m ? sg : 0.f);
                anyl |= (m && lv == c);
            }
            g_pr[(ncbase + c)*PP + p] = maxp + CLIPMIN;
            g_la[(ncbase + c)*PP + p] = anyl ? 1.f : 0.f;
        }
    }

    double b = (double)bce_acc, v = (double)valid;
    #pragma unroll
    for (int o = 16; o > 0; o >>= 1) {
        b += __shfl_down_sync(FULLM, b, o);
        v += __shfl_down_sync(FULLM, v, o);
    }
    __shared__ double sb[4], sv[4];
    const int lane = threadIdx.x & 31, wid = threadIdx.x >> 5;
    if (lane == 0) { sb[wid] = b; sv[wid] = v; }
    __syncthreads();
    if (threadIdx.x == 0) {
        atomicAdd(&g_bce,   sb[0] + sb[1] + sb[2] + sb[3]);
        atomicAdd(&g_valid, sv[0] + sv[1] + sv[2] + sv[3]);
    }
}

// ------------------------- kernel 2a: self Grams (column-rolling) ----------
// Thread = one column j; iterates rows of its chunk keeping the 3x3 window in
// registers: 3 coalesced loads + 54 FFMA per sample. V=0: la, V=1: pr.
template<int V>
__global__ void __launch_bounds__(192)
k_gram_self() {
    const int nc = blockIdx.x;
    const int j  = threadIdx.x;
    const int i0 = blockIdx.y * ROWCH;
    const int i1 = (i0 + ROWCH < NH) ? (i0 + ROWCH) : NH;

    float acc[54];
    #pragma unroll
    for (int k = 0; k < 54; k++) acc[k] = 0.f;

    if (j < NH) {
        const float* __restrict__ A =
            ((V == 1) ? g_pr : g_la) + (size_t)nc * PP + i0*PH + j;
        float w[3][3];
        #pragma unroll
        for (int c = 0; c < 3; c++) w[0][c] = A[c];
        A += PH;
        #pragma unroll
        for (int c = 0; c < 3; c++) w[1][c] = A[c];
        A += PH;
        #pragma unroll 2
        for (int i = i0; i < i1; i++) {
            #pragma unroll
            for (int c = 0; c < 3; c++) w[2][c] = A[c];
            A += PH;
            int k = 0;
            #pragma unroll
            for (int d = 0; d < 9; d++) {
                const float ad = w[d/3][d%3];
                #pragma unroll
                for (int e = d; e < 9; e++)
                    acc[k++] += ad * w[e/3][e%3];
            }
            #pragma unroll
            for (int d = 0; d < 9; d++) acc[45 + d] += w[d/3][d%3];
            #pragma unroll
            for (int c = 0; c < 3; c++) { w[0][c] = w[1][c]; w[1][c] = w[2][c]; }
        }
    }

    // float butterfly reduce per accumulator; atomics spread across lanes
    const int lane = threadIdx.x & 31;
    double* __restrict__ out = g_gram + (size_t)(nc*3 + V) * 81;
    #pragma unroll
    for (int k = 0; k < 54; k++) {
        float x = acc[k];
        #pragma unroll
        for (int o = 16; o > 0; o >>= 1) x += __shfl_xor_sync(FULLM, x, o);
        if (lane == (k & 31)) atomicAdd(&out[k], (double)x);
    }
}

// ------------------------- kernel 2b: cross Gram la x pr -------------------
__global__ void __launch_bounds__(192)
k_gram_cross() {
    const int nc = blockIdx.x;
    const int j  = threadIdx.x;
    const int i0 = blockIdx.y * ROWCH;
    const int i1 = (i0 + ROWCH < NH) ? (i0 + ROWCH) : NH;

    float acc[81];
    #pragma unroll
    for (int k = 0; k < 81; k++) acc[k] = 0.f;

    if (j < NH) {
        const float* __restrict__ A = g_la + (size_t)nc * PP + i0*PH + j;
        const float* __restrict__ B = g_pr + (size_t)nc * PP + i0*PH + j;
        float wa[3][3], wb[3][3];
        #pragma unroll
        for (int c = 0; c < 3; c++) { wa[0][c] = A[c]; wb[0][c] = B[c]; }
        A += PH; B += PH;
        #pragma unroll
        for (int c = 0; c < 3; c++) { wa[1][c] = A[c]; wb[1][c] = B[c]; }
        A += PH; B += PH;
        #pragma unroll 1
        for (int i = i0; i < i1; i++) {
            #pragma unroll
            for (int c = 0; c < 3; c++) { wa[2][c] = A[c]; wb[2][c] = B[c]; }
            A += PH; B += PH;
            #pragma unroll
            for (int d = 0; d < 9; d++) {
                const float ad = wa[d/3][d%3];
                #pragma unroll
                for (int e = 0; e < 9; e++)
                    acc[d*9 + e] += ad * wb[e/3][e%3];
            }
            #pragma unroll
            for (int c = 0; c < 3; c++) {
                wa[0][c] = wa[1][c]; wa[1][c] = wa[2][c];
                wb[0][c] = wb[1][c]; wb[1][c] = wb[2][c];
            }
        }
    }

    const int lane = threadIdx.x & 31;
    double* __restrict__ out = g_gram + (size_t)(nc*3 + 2) * 81;
    #pragma unroll
    for (int k = 0; k < 81; k++) {
        float x = acc[k];
        #pragma unroll
        for (int o = 16; o > 0; o >>= 1) x += __shfl_xor_sync(FULLM, x, o);
        if (lane == (k & 31)) atomicAdd(&out[k], (double)x);
    }
}

// ------------------------- kernel 3: warp-parallel linear algebra ----------
__global__ void __launch_bounds__(32)
k_finalize() {
    const int nc = blockIdx.x;
    const int d  = threadIdx.x;
    const int dd = (d < 9) ? d : 0;

    const double* __restrict__ G0 = g_gram + (size_t)(nc*3 + 0)*81;
    const double* __restrict__ G1 = g_gram + (size_t)(nc*3 + 1)*81;
    const double* __restrict__ G2 = g_gram + (size_t)(nc*3 + 2)*81;

    const double invM = 1.0 / (double)M_;
    const double sla_d = G0[45 + dd], spr_d = G1[45 + dd];

    double Cr[9], Pr[9], Br[9];
    #pragma unroll
    for (int e = 0; e < 9; e++) {
        const int lo = (dd < e) ? dd : e;
        const int hi = (dd < e) ? e : dd;
        const int tri = lo*9 - (lo*(lo-1))/2 + (hi - lo);
        const double sla_e = G0[45 + e], spr_e = G1[45 + e];
        Cr[e] = G0[tri] - sla_d*sla_e*invM + ((e == dd) ? ALPHA : 0.0);
        Pr[e] = G1[tri] - spr_d*spr_e*invM + ((e == dd) ? ALPHA : 0.0);
        Br[e] = G2[dd*9 + e] - sla_d*spr_e*invM;
    }

    double Lr[9];
    #pragma unroll
    for (int k = 0; k < 9; k++) {
        const double pkk = __shfl_sync(FULLM, Pr[k], k);
        const double lkk = sqrt(fmax(pkk, 1e-300));
        const double ldk = Pr[k] * (1.0 / lkk);
        Lr[k] = ldk;
        #pragma unroll
        for (int j = 0; j < 9; j++)
            if (j > k) Pr[j] -= ldk * __shfl_sync(FULLM, ldk, j);
    }

    double Wr[9];
    #pragma unroll
    for (int e = 0; e < 9; e++) {
        double s = Br[e];
        #pragma unroll
        for (int k = 0; k < 9; k++)
            if (k < e) s -= Wr[k] * __shfl_sync(FULLM, Lr[k], e);
        const double lee = __shfl_sync(FULLM, Lr[e], e);
        Wr[e] = s * (1.0 / lee);
    }

    #pragma unroll
    for (int e = 0; e < 9; e++) {
        double s = 0.0;
        #pragma unroll
        for (int k = 0; k < 9; k++)
            s += Wr[k] * __shfl_sync(FULLM, Wr[k], e);
        Cr[e] -= s;
    }

    double lsum = 0.0;
    #pragma unroll
    for (int k = 0; k < 9; k++) {
        const double akk = __shfl_sync(FULLM, Cr[k], k);
        const double lkk = sqrt(fmax(akk, 1e-300));
        lsum += log(lkk + 1e-8);
        const double ldk = Cr[k] * (1.0 / lkk);
        #pragma unroll
        for (int j = 0; j < 9; j++)
            if (j > k) Cr[j] -= ldk * __shfl_sync(FULLM, ldk, j);
    }

    if (d == 0) atomicAdd(&g_rmi, lsum);
}

// ------------------------- kernel 4: combine --------------------------------
__global__ void k_out(float* __restrict__ outp) {
    const double rmi_total = g_rmi / (double)(N_ * 9);
    const double bce_loss  = g_bce / (g_valid + 1.0);
    outp[0] = (float)(0.5 * bce_loss + 0.5 * rmi_total);
}

// ------------------------- launch ------------------------------------------
extern "C" void kernel_launch(void* const* d_in, const int* in_sizes, int n_in,
                              void* d_out, int out_size) {
    const float* logits = (const float*)d_in[0];
    const void*  labels = d_in[1];

    k_init<<<(GRAMSZ + 255) / 256, 256>>>(labels);
    dim3 g1((PP + 127) / 128, N_);
    k_pool_bce<<<g1, 128>>>(logits, labels);
    dim3 g2(NC, RSPLIT);
    k_gram_self<0><<<g2, 192>>>();
    k_gram_self<1><<<g2, 192>>>();
    k_gram_cross<<<g2, 192>>>();
    k_finalize<<<NC, 32>>>();
    k_out<<<1, 1>>>((float*)d_out);
}

// round 6
// speedup vs baseline: 3.6737x; 1.4049x over previous
#include <cuda_runtime.h>
#include <math.h>
#include <float.h>

#define N_      4
#define C_      21
#define H_      512
#define W_      512
#define HW      (H_*W_)
#define PH      171
#define PP      (PH*PH)      // 29241
#define NH      169
#define M_      (NH*NH)      // 28561
#define NC      (N_*C_)      // 84
#define ALPHA   5e-4
#define CLIPMIN 1e-6f
#define RSPLIT  8
#define ROWCH   ((NH + RSPLIT - 1) / RSPLIT)   // 22
#define GRAMSZ  (NC*3*81)
#define FULLM   0xffffffffu

// ------------------------- device scratch ----------------------------------
__device__ float  g_la[NC*PP];
__device__ float  g_pr[NC*PP];
__device__ double g_gram[GRAMSZ];
__device__ double g_bce;
__device__ double g_valid;
__device__ double g_rmi;
__device__ int    g_lab64;

// ------------------------- kernel 0: zero grams + dtype sniff --------------
__global__ void k_init(const void* lab) {
    const int i = blockIdx.x * blockDim.x + threadIdx.x;
    if (i < GRAMSZ) g_gram[i] = 0.0;
    if (i == 0) {
        const int* p = (const int*)lab;
        bool is64 = true;
        #pragma unroll 1
        for (int k = 0; k < 64; k++)
            if (p[2*k + 1] != 0) { is64 = false; break; }
        g_lab64 = is64 ? 1 : 0;
        g_bce = 0.0; g_valid = 0.0; g_rmi = 0.0;
    }
}

// ------------------------- kernel 1: fused max-pool + BCE ------------------
// One thread per pooled cell. All per-slot arrays are indexed with
// compile-time constants inside fully-unrolled loops -> registers.
// MUFU diet: sum_c softplus = sum relu + log prod(1+e^{-|x|})  (1 EX2/elem,
// 1 LG2 per cell-class); pooled sigmoid via sigmoid(max logit) (monotone).
__global__ void __launch_bounds__(128)
k_pool_bce(const float* __restrict__ logits, const void* __restrict__ labv) {
    const int p = blockIdx.x * blockDim.x + threadIdx.x;
    const int n = blockIdx.y;

    float bce_acc = 0.f;
    int   valid   = 0;

    if (p < PP) {
        const int i  = p / PH, j = p - i * PH;
        const int y0 = 3*i - 1, x0 = 3*j - 1;

        const bool is64 = (g_lab64 != 0);
        const long long* L64 = (const long long*)labv;
        const int*       L32 = (const int*)labv;

        int offk[9], labk[9];
        unsigned vmask = 0, labmask = 0;
        #pragma unroll
        for (int s = 0; s < 9; s++) {
            const int y = y0 + s/3, x = x0 + (s%3);
            const bool inb = ((unsigned)y < H_) && ((unsigned)x < W_);
            const int pix = inb ? (y*W_ + x) : 0;
            int lv = -1;
            if (inb) {
                const int gidx = n*HW + pix;
                lv = is64 ? (int)L64[gidx] : L32[gidx];
            }
            const bool val = inb && ((unsigned)lv < (unsigned)C_);
            offk[s] = pix;
            labk[s] = val ? lv : -1;
            if (val) { valid++; vmask |= (1u << s); labmask |= (1u << lv); }
        }

        const int ncbase = n * C_;
        const float* __restrict__ base = logits + (size_t)ncbase * HW;

        #pragma unroll 1
        for (int c = 0; c < C_; c++) {
            const float* __restrict__ px = base + (size_t)c * HW;
            float maxv = -FLT_MAX;
            float prod = 1.f;          // prod over valid pixels of (1+e^{-|x|})
            float racc = 0.f;          // sum relu(x) - onehot*x
            #pragma unroll
            for (int k = 0; k < 9; k++) {
                float xv = px[offk[k]];
                xv = ((vmask >> k) & 1u) ? xv : -FLT_MAX;  // neutral element
                maxv = fmaxf(maxv, xv);
                const float t = __expf(-fabsf(xv));        // 0 when invalid
                prod = fmaf(prod, t, prod);                // *= (1+t)
                racc += fmaxf(xv, 0.f);
                racc -= (labk[k] == c) ? xv : 0.f;
            }
            bce_acc += racc + __logf(prod);
            // pooled prob: sigmoid(maxv); maxv=-FLT_MAX (no valid) -> sg=0
            const float t = __expf(-fabsf(maxv));
            const float u = __fdividef(1.f, 1.f + t);
            const float sg = (maxv >= 0.f) ? u : t * u;
            g_pr[(ncbase + c)*PP + p] = sg + CLIPMIN;
            g_la[(ncbase + c)*PP + p] = ((labmask >> c) & 1u) ? 1.f : 0.f;
        }
    }

    double b = (double)bce_acc, v = (double)valid;
    #pragma unroll
    for (int o = 16; o > 0; o >>= 1) {
        b += __shfl_down_sync(FULLM, b, o);
        v += __shfl_down_sync(FULLM, v, o);
    }
    __shared__ double sb[4], sv[4];
    const int lane = threadIdx.x & 31, wid = threadIdx.x >> 5;
    if (lane == 0) { sb[wid] = b; sv[wid] = v; }
    __syncthreads();
    if (threadIdx.x == 0) {
        atomicAdd(&g_bce,   sb[0] + sb[1] + sb[2] + sb[3]);
        atomicAdd(&g_valid, sv[0] + sv[1] + sv[2] + sv[3]);
    }
}

// ------------------------- kernel 2a: self Grams (column-rolling, R5) ------
template<int V>
__global__ void __launch_bounds__(192)
k_gram_self() {
    const int nc = blockIdx.x;
    const int j  = threadIdx.x;
    const int i0 = blockIdx.y * ROWCH;
    const int i1 = (i0 + ROWCH < NH) ? (i0 + ROWCH) : NH;

    float acc[54];
    #pragma unroll
    for (int k = 0; k < 54; k++) acc[k] = 0.f;

    if (j < NH) {
        const float* __restrict__ A =
            ((V == 1) ? g_pr : g_la) + (size_t)nc * PP + i0*PH + j;
        float w[3][3];
        #pragma unroll
        for (int c = 0; c < 3; c++) w[0][c] = A[c];
        A += PH;
        #pragma unroll
        for (int c = 0; c < 3; c++) w[1][c] = A[c];
        A += PH;
        #pragma unroll 2
        for (int i = i0; i < i1; i++) {
            #pragma unroll
            for (int c = 0; c < 3; c++) w[2][c] = A[c];
            A += PH;
            int k = 0;
            #pragma unroll
            for (int d = 0; d < 9; d++) {
                const float ad = w[d/3][d%3];
                #pragma unroll
                for (int e = d; e < 9; e++)
                    acc[k++] += ad * w[e/3][e%3];
            }
            #pragma unroll
            for (int d = 0; d < 9; d++) acc[45 + d] += w[d/3][d%3];
            #pragma unroll
            for (int c = 0; c < 3; c++) { w[0][c] = w[1][c]; w[1][c] = w[2][c]; }
        }
    }

    const int lane = threadIdx.x & 31;
    double* __restrict__ out = g_gram + (size_t)(nc*3 + V) * 81;
    #pragma unroll
    for (int k = 0; k < 54; k++) {
        float x = acc[k];
        #pragma unroll
        for (int o = 16; o > 0; o >>= 1) x += __shfl_xor_sync(FULLM, x, o);
        if (lane == (k & 31)) atomicAdd(&out[k], (double)x);
    }
}

// ------------------------- kernel 2b: cross Gram la x pr (R5) --------------
__global__ void __launch_bounds__(192)
k_gram_cross() {
    const int nc = blockIdx.x;
    const int j  = threadIdx.x;
    const int i0 = blockIdx.y * ROWCH;
    const int i1 = (i0 + ROWCH < NH) ? (i0 + ROWCH) : NH;

    float acc[81];
    #pragma unroll
    for (int k = 0; k < 81; k++) acc[k] = 0.f;

    if (j < NH) {
        const float* __restrict__ A = g_la + (size_t)nc * PP + i0*PH + j;
        const float* __restrict__ B = g_pr + (size_t)nc * PP + i0*PH + j;
        float wa[3][3], wb[3][3];
        #pragma unroll
        for (int c = 0; c < 3; c++) { wa[0][c] = A[c]; wb[0][c] = B[c]; }
        A += PH; B += PH;
        #pragma unroll
        for (int c = 0; c < 3; c++) { wa[1][c] = A[c]; wb[1][c] = B[c]; }
        A += PH; B += PH;
        #pragma unroll 1
        for (int i = i0; i < i1; i++) {
            #pragma unroll
            for (int c = 0; c < 3; c++) { wa[2][c] = A[c]; wb[2][c] = B[c]; }
            A += PH; B += PH;
            #pragma unroll
            for (int d = 0; d < 9; d++) {
                const float ad = wa[d/3][d%3];
                #pragma unroll
                for (int e = 0; e < 9; e++)
                    acc[d*9 + e] += ad * wb[e/3][e%3];
            }
            #pragma unroll
            for (int c = 0; c < 3; c++) {
                wa[0][c] = wa[1][c]; wa[1][c] = wa[2][c];
                wb[0][c] = wb[1][c]; wb[1][c] = wb[2][c];
            }
        }
    }

    const int lane = threadIdx.x & 31;
    double* __restrict__ out = g_gram + (size_t)(nc*3 + 2) * 81;
    #pragma unroll
    for (int k = 0; k < 81; k++) {
        float x = acc[k];
        #pragma unroll
        for (int o = 16; o > 0; o >>= 1) x += __shfl_xor_sync(FULLM, x, o);
        if (lane == (k & 31)) atomicAdd(&out[k], (double)x);
    }
}

// ------------------------- kernel 3: warp-parallel linear algebra ----------
// rsqrt-based Cholesky (no fp64 divides), single log of diag product.
__global__ void __launch_bounds__(32)
k_finalize() {
    const int nc = blockIdx.x;
    const int d  = threadIdx.x;
    const int dd = (d < 9) ? d : 0;

    const double* __restrict__ G0 = g_gram + (size_t)(nc*3 + 0)*81;
    const double* __restrict__ G1 = g_gram + (size_t)(nc*3 + 1)*81;
    const double* __restrict__ G2 = g_gram + (size_t)(nc*3 + 2)*81;

    const double invM = 1.0 / (double)M_;
    const double sla_d = G0[45 + dd], spr_d = G1[45 + dd];

    double Cr[9], Pr[9], Br[9];
    #pragma unroll
    for (int e = 0; e < 9; e++) {
        const int lo = (dd < e) ? dd : e;
        const int hi = (dd < e) ? e : dd;
        const int tri = lo*9 - (lo*(lo-1))/2 + (hi - lo);
        const double sla_e = G0[45 + e], spr_e = G1[45 + e];
        Cr[e] = G0[tri] - sla_d*sla_e*invM + ((e == dd) ? ALPHA : 0.0);
        Pr[e] = G1[tri] - spr_d*spr_e*invM + ((e == dd) ? ALPHA : 0.0);
        Br[e] = G2[dd*9 + e] - sla_d*spr_e*invM;
    }

    // Cholesky of P; lane d ends with Lr[k]=L[d][k]; Dinv[k]=1/L[k][k] saved.
    double Lr[9], Dinv[9];
    #pragma unroll
    for (int k = 0; k < 9; k++) {
        const double pkk = __shfl_sync(FULLM, Pr[k], k);
        const double rs  = rsqrt(fmax(pkk, 1e-300));   // 1/sqrt(pkk) = 1/lkk
        const double ldk = Pr[k] * rs;
        Lr[k]   = ldk;
        Dinv[k] = rs;
        #pragma unroll
        for (int j = 0; j < 9; j++)
            if (j > k) Pr[j] -= ldk * __shfl_sync(FULLM, ldk, j);
    }

    // W = B L^{-T}: multiply by saved reciprocal diag (no divides)
    double Wr[9];
    #pragma unroll
    for (int e = 0; e < 9; e++) {
        double s = Br[e];
        #pragma unroll
        for (int k = 0; k < 9; k++)
            if (k < e) s -= Wr[k] * __shfl_sync(FULLM, Lr[k], e);
        Wr[e] = s * Dinv[e];
    }

    // A2 = Cla + alpha I - W W^T
    #pragma unroll
    for (int e = 0; e < 9; e++) {
        double s = 0.0;
        #pragma unroll
        for (int k = 0; k < 9; k++)
            s += Wr[k] * __shfl_sync(FULLM, Wr[k], e);
        Cr[e] -= s;
    }

    // Cholesky of A2; accumulate product of (diag + 1e-8), single log.
    double dprod = 1.0;
    #pragma unroll
    for (int k = 0; k < 9; k++) {
        const double akk = __shfl_sync(FULLM, Cr[k], k);
        const double as  = fmax(akk, 1e-300);
        const double rs  = rsqrt(as);
        const double lkk = as * rs;          // sqrt(akk)
        dprod *= (lkk + 1e-8);
        const double ldk = Cr[k] * rs;
        #pragma unroll
        for (int j = 0; j < 9; j++)
            if (j > k) Cr[j] -= ldk * __shfl_sync(FULLM, ldk, j);
    }

    if (d == 0) atomicAdd(&g_rmi, log(dprod));
}

// ------------------------- kernel 4: combine --------------------------------
__global__ void k_out(float* __restrict__ outp) {
    const double rmi_total = g_rmi / (double)(N_ * 9);
    const double bce_loss  = g_bce / (g_valid + 1.0);
    outp[0] = (float)(0.5 * bce_loss + 0.5 * rmi_total);
}

// ------------------------- launch ------------------------------------------
extern "C" void kernel_launch(void* const* d_in, const int* in_sizes, int n_in,
                              void* d_out, int out_size) {
    const float* logits = (const float*)d_in[0];
    const void*  labels = d_in[1];

    k_init<<<(GRAMSZ + 255) / 256, 256>>>(labels);
    dim3 g1((PP + 127) / 128, N_);
    k_pool_bce<<<g1, 128>>>(logits, labels);
    dim3 g2(NC, RSPLIT);
    k_gram_self<0><<<g2, 192>>>();
    k_gram_self<1><<<g2, 192>>>();
    k_gram_cross<<<g2, 192>>>();
    k_finalize<<<NC, 32>>>();
    k_out<<<1, 1>>>((float*)d_out);
}

// round 7
// speedup vs baseline: 4.0264x; 1.0960x over previous
#include <cuda_runtime.h>
#include <math.h>
#include <float.h>

#define N_      4
#define C_      21
#define H_      512
#define W_      512
#define HW      (H_*W_)
#define PH      171
#define PP      (PH*PH)      // 29241
#define NH      169
#define M_      (NH*NH)      // 28561
#define NC      (N_*C_)      // 84
#define ALPHA   5e-4
#define CLIPMIN 1e-6f
#define RSPLIT  8
#define ROWCH   ((NH + RSPLIT - 1) / RSPLIT)   // 22
#define GRAMSZ  (NC*3*81)
#define FULLM   0xffffffffu

// ------------------------- device scratch ----------------------------------
__device__ float  g_la[NC*PP];
__device__ float  g_pr[NC*PP];
__device__ double g_gram[GRAMSZ];
__device__ double g_bce;
__device__ double g_valid;
__device__ double g_rmi;
__device__ int    g_lab64;

// ------------------------- kernel 0: zero grams + dtype sniff --------------
__global__ void k_init(const void* lab) {
    const int i = blockIdx.x * blockDim.x + threadIdx.x;
    if (i < GRAMSZ) g_gram[i] = 0.0;
    if (i == 0) {
        const int* p = (const int*)lab;
        bool is64 = true;
        #pragma unroll 1
        for (int k = 0; k < 64; k++)
            if (p[2*k + 1] != 0) { is64 = false; break; }
        g_lab64 = is64 ? 1 : 0;
        g_bce = 0.0; g_valid = 0.0; g_rmi = 0.0;
    }
}

// ------------------------- kernel 1: fused max-pool + BCE (R6) -------------
__global__ void __launch_bounds__(128)
k_pool_bce(const float* __restrict__ logits, const void* __restrict__ labv) {
    const int p = blockIdx.x * blockDim.x + threadIdx.x;
    const int n = blockIdx.y;

    float bce_acc = 0.f;
    int   valid   = 0;

    if (p < PP) {
        const int i  = p / PH, j = p - i * PH;
        const int y0 = 3*i - 1, x0 = 3*j - 1;

        const bool is64 = (g_lab64 != 0);
        const long long* L64 = (const long long*)labv;
        const int*       L32 = (const int*)labv;

        int offk[9], labk[9];
        unsigned vmask = 0, labmask = 0;
        #pragma unroll
        for (int s = 0; s < 9; s++) {
            const int y = y0 + s/3, x = x0 + (s%3);
            const bool inb = ((unsigned)y < H_) && ((unsigned)x < W_);
            const int pix = inb ? (y*W_ + x) : 0;
            int lv = -1;
            if (inb) {
                const int gidx = n*HW + pix;
                lv = is64 ? (int)L64[gidx] : L32[gidx];
            }
            const bool val = inb && ((unsigned)lv < (unsigned)C_);
            offk[s] = pix;
            labk[s] = val ? lv : -1;
            if (val) { valid++; vmask |= (1u << s); labmask |= (1u << lv); }
        }

        const int ncbase = n * C_;
        const float* __restrict__ base = logits + (size_t)ncbase * HW;

        #pragma unroll 1
        for (int c = 0; c < C_; c++) {
            const float* __restrict__ px = base + (size_t)c * HW;
            float maxv = -FLT_MAX;
            float prod = 1.f;
            float racc = 0.f;
            #pragma unroll
            for (int k = 0; k < 9; k++) {
                float xv = px[offk[k]];
                xv = ((vmask >> k) & 1u) ? xv : -FLT_MAX;
                maxv = fmaxf(maxv, xv);
                const float t = __expf(-fabsf(xv));
                prod = fmaf(prod, t, prod);
                racc += fmaxf(xv, 0.f);
                racc -= (labk[k] == c) ? xv : 0.f;
            }
            bce_acc += racc + __logf(prod);
            const float t = __expf(-fabsf(maxv));
            const float u = __fdividef(1.f, 1.f + t);
            const float sg = (maxv >= 0.f) ? u : t * u;
            g_pr[(ncbase + c)*PP + p] = sg + CLIPMIN;
            g_la[(ncbase + c)*PP + p] = ((labmask >> c) & 1u) ? 1.f : 0.f;
        }
    }

    double b = (double)bce_acc, v = (double)valid;
    #pragma unroll
    for (int o = 16; o > 0; o >>= 1) {
        b += __shfl_down_sync(FULLM, b, o);
        v += __shfl_down_sync(FULLM, v, o);
    }
    __shared__ double sb[4], sv[4];
    const int lane = threadIdx.x & 31, wid = threadIdx.x >> 5;
    if (lane == 0) { sb[wid] = b; sv[wid] = v; }
    __syncthreads();
    if (threadIdx.x == 0) {
        atomicAdd(&g_bce,   sb[0] + sb[1] + sb[2] + sb[3]);
        atomicAdd(&g_valid, sv[0] + sv[1] + sv[2] + sv[3]);
    }
}

// ------------------------- kernel 2a: self Grams (pipelined, z-merged) -----
// blockIdx.z: 0 -> la Gram, 1 -> pr Gram. Column-rolling window with a
// one-iteration load prefetch: row i+3 is issued before the 63-FMA body of
// row i, covering L2 latency with arithmetic.
__global__ void __launch_bounds__(192)
k_gram_self() {
    const int nc = blockIdx.x;
    const int V  = blockIdx.z;
    const int j  = threadIdx.x;
    const int i0 = blockIdx.y * ROWCH;
    const int i1 = (i0 + ROWCH < NH) ? (i0 + ROWCH) : NH;

    float acc[54];
    #pragma unroll
    for (int k = 0; k < 54; k++) acc[k] = 0.f;

    if (j < NH) {
        const float* __restrict__ A =
            (V ? g_pr : g_la) + (size_t)nc * PP + i0*PH + j;
        float w0[3], w1[3], nxt[3];
        #pragma unroll
        for (int c = 0; c < 3; c++) w0[c] = A[c];
        A += PH;
        #pragma unroll
        for (int c = 0; c < 3; c++) w1[c] = A[c];
        A += PH;
        #pragma unroll
        for (int c = 0; c < 3; c++) nxt[c] = A[c];
        A += PH;

        #pragma unroll 2
        for (int i = i0; i < i1; i++) {
            float w2[3];
            #pragma unroll
            for (int c = 0; c < 3; c++) w2[c] = nxt[c];
            // prefetch row i+3 (guarded; lands while FMAs below execute)
            const bool more = (i + 1 < i1);
            #pragma unroll
            for (int c = 0; c < 3; c++) nxt[c] = more ? A[c] : 0.f;
            A += PH;

            float a[9] = { w0[0], w0[1], w0[2],
                           w1[0], w1[1], w1[2],
                           w2[0], w2[1], w2[2] };
            int k = 0;
            #pragma unroll
            for (int d = 0; d < 9; d++) {
                #pragma unroll
                for (int e = d; e < 9; e++)
                    acc[k++] += a[d] * a[e];
            }
            #pragma unroll
            for (int d = 0; d < 9; d++) acc[45 + d] += a[d];

            #pragma unroll
            for (int c = 0; c < 3; c++) { w0[c] = w1[c]; w1[c] = w2[c]; }
        }
    }

    const int lane = threadIdx.x & 31;
    double* __restrict__ out = g_gram + (size_t)(nc*3 + V) * 81;
    #pragma unroll
    for (int k = 0; k < 54; k++) {
        float x = acc[k];
        #pragma unroll
        for (int o = 16; o > 0; o >>= 1) x += __shfl_xor_sync(FULLM, x, o);
        if (lane == (k & 31)) atomicAdd(&out[k], (double)x);
    }
}

// ------------------------- kernel 2b: cross Gram la x pr (pipelined) -------
__global__ void __launch_bounds__(192)
k_gram_cross() {
    const int nc = blockIdx.x;
    const int j  = threadIdx.x;
    const int i0 = blockIdx.y * ROWCH;
    const int i1 = (i0 + ROWCH < NH) ? (i0 + ROWCH) : NH;

    float acc[81];
    #pragma unroll
    for (int k = 0; k < 81; k++) acc[k] = 0.f;

    if (j < NH) {
        const float* __restrict__ A = g_la + (size_t)nc * PP + i0*PH + j;
        const float* __restrict__ B = g_pr + (size_t)nc * PP + i0*PH + j;
        float wa0[3], wa1[3], na[3];
        float wb0[3], wb1[3], nb[3];
        #pragma unroll
        for (int c = 0; c < 3; c++) { wa0[c] = A[c]; wb0[c] = B[c]; }
        A += PH; B += PH;
        #pragma unroll
        for (int c = 0; c < 3; c++) { wa1[c] = A[c]; wb1[c] = B[c]; }
        A += PH; B += PH;
        #pragma unroll
        for (int c = 0; c < 3; c++) { na[c] = A[c]; nb[c] = B[c]; }
        A += PH; B += PH;

        #pragma unroll 1
        for (int i = i0; i < i1; i++) {
            float wa2[3], wb2[3];
            #pragma unroll
            for (int c = 0; c < 3; c++) { wa2[c] = na[c]; wb2[c] = nb[c]; }
            const bool more = (i + 1 < i1);
            #pragma unroll
            for (int c = 0; c < 3; c++) {
                na[c] = more ? A[c] : 0.f;
                nb[c] = more ? B[c] : 0.f;
            }
            A += PH; B += PH;

            float a[9] = { wa0[0], wa0[1], wa0[2],
                           wa1[0], wa1[1], wa1[2],
                           wa2[0], wa2[1], wa2[2] };
            float b[9] = { wb0[0], wb0[1], wb0[2],
                           wb1[0], wb1[1], wb1[2],
                           wb2[0], wb2[1], wb2[2] };
            #pragma unroll
            for (int d = 0; d < 9; d++)
                #pragma unroll
                for (int e = 0; e < 9; e++)
                    acc[d*9 + e] += a[d] * b[e];

            #pragma unroll
            for (int c = 0; c < 3; c++) {
                wa0[c] = wa1[c]; wa1[c] = wa2[c];
                wb0[c] = wb1[c]; wb1[c] = wb2[c];
            }
        }
    }

    const int lane = threadIdx.x & 31;
    double* __restrict__ out = g_gram + (size_t)(nc*3 + 2) * 81;
    #pragma unroll
    for (int k = 0; k < 81; k++) {
        float x = acc[k];
        #pragma unroll
        for (int o = 16; o > 0; o >>= 1) x += __shfl_xor_sync(FULLM, x, o);
        if (lane == (k & 31)) atomicAdd(&out[k], (double)x);
    }
}

// ------------------------- kernel 3: warp-parallel linear algebra (R6) -----
__global__ void __launch_bounds__(32)
k_finalize() {
    const int nc = blockIdx.x;
    const int d  = threadIdx.x;
    const int dd = (d < 9) ? d : 0;

    const double* __restrict__ G0 = g_gram + (size_t)(nc*3 + 0)*81;
    const double* __restrict__ G1 = g_gram + (size_t)(nc*3 + 1)*81;
    const double* __restrict__ G2 = g_gram + (size_t)(nc*3 + 2)*81;

    const double invM = 1.0 / (double)M_;
    const double sla_d = G0[45 + dd], spr_d = G1[45 + dd];

    double Cr[9], Pr[9], Br[9];
    #pragma unroll
    for (int e = 0; e < 9; e++) {
        const int lo = (dd < e) ? dd : e;
        const int hi = (dd < e) ? e : dd;
        const int tri = lo*9 - (lo*(lo-1))/2 + (hi - lo);
        const double sla_e = G0[45 + e], spr_e = G1[45 + e];
        Cr[e] = G0[tri] - sla_d*sla_e*invM + ((e == dd) ? ALPHA : 0.0);
        Pr[e] = G1[tri] - spr_d*spr_e*invM + ((e == dd) ? ALPHA : 0.0);
        Br[e] = G2[dd*9 + e] - sla_d*spr_e*invM;
    }

    double Lr[9], Dinv[9];
    #pragma unroll
    for (int k = 0; k < 9; k++) {
        const double pkk = __shfl_sync(FULLM, Pr[k], k);
        const double rs  = rsqrt(fmax(pkk, 1e-300));
        const double ldk = Pr[k] * rs;
        Lr[k]   = ldk;
        Dinv[k] = rs;
        #pragma unroll
        for (int j = 0; j < 9; j++)
            if (j > k) Pr[j] -= ldk * __shfl_sync(FULLM, ldk, j);
    }

    double Wr[9];
    #pragma unroll
    for (int e = 0; e < 9; e++) {
        double s = Br[e];
        #pragma unroll
        for (int k = 0; k < 9; k++)
            if (k < e) s -= Wr[k] * __shfl_sync(FULLM, Lr[k], e);
        Wr[e] = s * Dinv[e];
    }

    #pragma unroll
    for (int e = 0; e < 9; e++) {
        double s = 0.0;
        #pragma unroll
        for (int k = 0; k < 9; k++)
            s += Wr[k] * __shfl_sync(FULLM, Wr[k], e);
        Cr[e] -= s;
    }

    double dprod = 1.0;
    #pragma unroll
    for (int k = 0; k < 9; k++) {
        const double akk = __shfl_sync(FULLM, Cr[k], k);
        const double as  = fmax(akk, 1e-300);
        const double rs  = rsqrt(as);
        const double lkk = as * rs;
        dprod *= (lkk + 1e-8);
        const double ldk = Cr[k] * rs;
        #pragma unroll
        for (int j = 0; j < 9; j++)
            if (j > k) Cr[j] -= ldk * __shfl_sync(FULLM, ldk, j);
    }

    if (d == 0) atomicAdd(&g_rmi, log(dprod));
}

// ------------------------- kernel 4: combine --------------------------------
__global__ void k_out(float* __restrict__ outp) {
    const double rmi_total = g_rmi / (double)(N_ * 9);
    const double bce_loss  = g_bce / (g_valid + 1.0);
    outp[0] = (float)(0.5 * bce_loss + 0.5 * rmi_total);
}

// ------------------------- launch ------------------------------------------
extern "C" void kernel_launch(void* const* d_in, const int* in_sizes, int n_in,
                              void* d_out, int out_size) {
    const float* logits = (const float*)d_in[0];
    const void*  labels = d_in[1];

    k_init<<<(GRAMSZ + 255) / 256, 256>>>(labels);
    dim3 g1((PP + 127) / 128, N_);
    k_pool_bce<<<g1, 128>>>(logits, labels);
    dim3 gs(NC, RSPLIT, 2);
    k_gram_self<<<gs, 192>>>();
    dim3 gc(NC, RSPLIT);
    k_gram_cross<<<gc, 192>>>();
    k_finalize<<<NC, 32>>>();
    k_out<<<1, 1>>>((float*)d_out);
}

// round 8
// speedup vs baseline: 4.6417x; 1.1528x over previous
#include <cuda_runtime.h>
#include <math.h>
#include <float.h>

#define N_      4
#define C_      21
#define H_      512
#define W_      512
#define HW      (H_*W_)
#define PH      171
#define PP      (PH*PH)      // 29241
#define NH      169
#define M_      (NH*NH)      // 28561
#define NC      (N_*C_)      // 84
#define ALPHA   5e-4
#define CLIPMIN 1e-6f
#define RSPLIT  8
#define ROWCH   ((NH + RSPLIT - 1) / RSPLIT)   // 22
#define GRAMSZ  (NC*3*81)
#define FULLM   0xffffffffu

// ------------------------- device scratch ----------------------------------
// +PH padding: gram kernels prefetch one row beyond the last window row.
__device__ float  g_la[NC*PP + PH];
__device__ float  g_pr[NC*PP + PH];
__device__ double g_gram[GRAMSZ];
__device__ double g_bce;
__device__ double g_valid;
__device__ double g_rmi;
__device__ int    g_lab64;

// ------------------------- kernel 0: zero grams + dtype sniff --------------
__global__ void k_init(const void* lab) {
    const int i = blockIdx.x * blockDim.x + threadIdx.x;
    if (i < GRAMSZ) g_gram[i] = 0.0;
    if (i == 0) {
        const int* p = (const int*)lab;
        bool is64 = true;
        #pragma unroll 1
        for (int k = 0; k < 64; k++)
            if (p[2*k + 1] != 0) { is64 = false; break; }
        g_lab64 = is64 ? 1 : 0;
        g_bce = 0.0; g_valid = 0.0; g_rmi = 0.0;
    }
}

// ------------------------- kernel 1: fused max-pool + BCE (R6) -------------
__global__ void __launch_bounds__(128)
k_pool_bce(const float* __restrict__ logits, const void* __restrict__ labv) {
    const int p = blockIdx.x * blockDim.x + threadIdx.x;
    const int n = blockIdx.y;

    float bce_acc = 0.f;
    int   valid   = 0;

    if (p < PP) {
        const int i  = p / PH, j = p - i * PH;
        const int y0 = 3*i - 1, x0 = 3*j - 1;

        const bool is64 = (g_lab64 != 0);
        const long long* L64 = (const long long*)labv;
        const int*       L32 = (const int*)labv;

        int offk[9], labk[9];
        unsigned vmask = 0, labmask = 0;
        #pragma unroll
        for (int s = 0; s < 9; s++) {
            const int y = y0 + s/3, x = x0 + (s%3);
            const bool inb = ((unsigned)y < H_) && ((unsigned)x < W_);
            const int pix = inb ? (y*W_ + x) : 0;
            int lv = -1;
            if (inb) {
                const int gidx = n*HW + pix;
                lv = is64 ? (int)L64[gidx] : L32[gidx];
            }
            const bool val = inb && ((unsigned)lv < (unsigned)C_);
            offk[s] = pix;
            labk[s] = val ? lv : -1;
            if (val) { valid++; vmask |= (1u << s); labmask |= (1u << lv); }
        }

        const int ncbase = n * C_;
        const float* __restrict__ base = logits + (size_t)ncbase * HW;

        #pragma unroll 1
        for (int c = 0; c < C_; c++) {
            const float* __restrict__ px = base + (size_t)c * HW;
            float maxv = -FLT_MAX;
            float prod = 1.f;
            float racc = 0.f;
            #pragma unroll
            for (int k = 0; k < 9; k++) {
                float xv = px[offk[k]];
                xv = ((vmask >> k) & 1u) ? xv : -FLT_MAX;
                maxv = fmaxf(maxv, xv);
                const float t = __expf(-fabsf(xv));
                prod = fmaf(prod, t, prod);
                racc += fmaxf(xv, 0.f);
                racc -= (labk[k] == c) ? xv : 0.f;
            }
            bce_acc += racc + __logf(prod);
            const float t = __expf(-fabsf(maxv));
            const float u = __fdividef(1.f, 1.f + t);
            const float sg = (maxv >= 0.f) ? u : t * u;
            g_pr[(ncbase + c)*PP + p] = sg + CLIPMIN;
            g_la[(ncbase + c)*PP + p] = ((labmask >> c) & 1u) ? 1.f : 0.f;
        }
    }

    double b = (double)bce_acc, v = (double)valid;
    #pragma unroll
    for (int o = 16; o > 0; o >>= 1) {
        b += __shfl_down_sync(FULLM, b, o);
        v += __shfl_down_sync(FULLM, v, o);
    }
    __shared__ double sb[4], sv[4];
    const int lane = threadIdx.x & 31, wid = threadIdx.x >> 5;
    if (lane == 0) { sb[wid] = b; sv[wid] = v; }
    __syncthreads();
    if (threadIdx.x == 0) {
        atomicAdd(&g_bce,   sb[0] + sb[1] + sb[2] + sb[3]);
        atomicAdd(&g_valid, sv[0] + sv[1] + sv[2] + sv[3]);
    }
}

// ------------------------- gram bodies -------------------------------------
__device__ __forceinline__ void self_body(const float* __restrict__ A0,
                                          int i0, int i1,
                                          double* __restrict__ out, int j) {
    float acc[54];
    #pragma unroll
    for (int k = 0; k < 54; k++) acc[k] = 0.f;

    if (j < NH) {
        const float* __restrict__ A = A0 + i0*PH + j;
        float w0[3], w1[3], nxt[3];
        #pragma unroll
        for (int c = 0; c < 3; c++) w0[c] = A[c];
        A += PH;
        #pragma unroll
        for (int c = 0; c < 3; c++) w1[c] = A[c];
        A += PH;
        #pragma unroll
        for (int c = 0; c < 3; c++) nxt[c] = A[c];
        A += PH;

        #pragma unroll 2
        for (int i = i0; i < i1; i++) {
            float a[9] = { w0[0], w0[1], w0[2],
                           w1[0], w1[1], w1[2],
                           nxt[0], nxt[1], nxt[2] };
            // unguarded prefetch (arrays padded by one row)
            #pragma unroll
            for (int c = 0; c < 3; c++) nxt[c] = A[c];
            A += PH;

            int k = 0;
            #pragma unroll
            for (int d = 0; d < 9; d++)
                #pragma unroll
                for (int e = d; e < 9; e++)
                    acc[k++] += a[d] * a[e];
            #pragma unroll
            for (int d = 0; d < 9; d++) acc[45 + d] += a[d];

            #pragma unroll
            for (int c = 0; c < 3; c++) { w0[c] = w1[c]; w1[c] = a[6 + c]; }
        }
    }

    const int lane = threadIdx.x & 31;
    #pragma unroll
    for (int k = 0; k < 54; k++) {
        float x = acc[k];
        #pragma unroll
        for (int o = 16; o > 0; o >>= 1) x += __shfl_xor_sync(FULLM, x, o);
        if (lane == (k & 31)) atomicAdd(&out[k], (double)x);
    }
}

template<int EL, int NE>
__device__ __forceinline__ void cross_body(const float* __restrict__ Ab,
                                           const float* __restrict__ Bb,
                                           int i0, int i1,
                                           double* __restrict__ out, int j) {
    float acc[9*NE];
    #pragma unroll
    for (int k = 0; k < 9*NE; k++) acc[k] = 0.f;

    if (j < NH) {
        const float* __restrict__ A = Ab + i0*PH + j;
        const float* __restrict__ B = Bb + i0*PH + j;
        float wa0[3], wa1[3], na[3];
        float wb0[3], wb1[3], nb[3];
        #pragma unroll
        for (int c = 0; c < 3; c++) { wa0[c] = A[c]; wb0[c] = B[c]; }
        A += PH; B += PH;
        #pragma unroll
        for (int c = 0; c < 3; c++) { wa1[c] = A[c]; wb1[c] = B[c]; }
        A += PH; B += PH;
        #pragma unroll
        for (int c = 0; c < 3; c++) { na[c] = A[c]; nb[c] = B[c]; }
        A += PH; B += PH;

        #pragma unroll 2
        for (int i = i0; i < i1; i++) {
            float a[9] = { wa0[0], wa0[1], wa0[2],
                           wa1[0], wa1[1], wa1[2],
                           na[0],  na[1],  na[2] };
            float b[9] = { wb0[0], wb0[1], wb0[2],
                           wb1[0], wb1[1], wb1[2],
                           nb[0],  nb[1],  nb[2] };
            // unguarded prefetch (padded arrays)
            #pragma unroll
            for (int c = 0; c < 3; c++) { na[c] = A[c]; nb[c] = B[c]; }
            A += PH; B += PH;

            #pragma unroll
            for (int d = 0; d < 9; d++)
                #pragma unroll
                for (int e = 0; e < NE; e++)
                    acc[d*NE + e] += a[d] * b[EL + e];

            #pragma unroll
            for (int c = 0; c < 3; c++) {
                wa0[c] = wa1[c]; wa1[c] = a[6 + c];
                wb0[c] = wb1[c]; wb1[c] = b[6 + c];
            }
        }
    }

    const int lane = threadIdx.x & 31;
    #pragma unroll
    for (int k = 0; k < 9*NE; k++) {
        float x = acc[k];
        #pragma unroll
        for (int o = 16; o > 0; o >>= 1) x += __shfl_xor_sync(FULLM, x, o);
        const int d = k / NE, e = EL + (k % NE);
        if (lane == (k & 31)) atomicAdd(&out[d*9 + e], (double)x);
    }
}

// ------------------------- kernel 2: all Grams, one launch -----------------
// blockIdx.z: 0 la-self, 1 pr-self, 2 cross e[0,5), 3 cross e[5,9)
__global__ void __launch_bounds__(192)
k_gram_all() {
    const int nc = blockIdx.x;
    const int z  = blockIdx.z;
    const int j  = threadIdx.x;
    const int i0 = blockIdx.y * ROWCH;
    const int i1 = (i0 + ROWCH < NH) ? (i0 + ROWCH) : NH;
    const size_t base = (size_t)nc * PP;
    double* __restrict__ out = g_gram + (size_t)(nc*3) * 81;

    if (z == 0)      self_body(g_la + base, i0, i1, out, j);
    else if (z == 1) self_body(g_pr + base, i0, i1, out + 81, j);
    else if (z == 2) cross_body<0,5>(g_la + base, g_pr + base, i0, i1, out + 162, j);
    else             cross_body<5,4>(g_la + base, g_pr + base, i0, i1, out + 162, j);
}

// ------------------------- kernel 3: warp-parallel linear algebra (R6) -----
__global__ void __launch_bounds__(32)
k_finalize() {
    const int nc = blockIdx.x;
    const int d  = threadIdx.x;
    const int dd = (d < 9) ? d : 0;

    const double* __restrict__ G0 = g_gram + (size_t)(nc*3 + 0)*81;
    const double* __restrict__ G1 = g_gram + (size_t)(nc*3 + 1)*81;
    const double* __restrict__ G2 = g_gram + (size_t)(nc*3 + 2)*81;

    const double invM = 1.0 / (double)M_;
    const double sla_d = G0[45 + dd], spr_d = G1[45 + dd];

    double Cr[9], Pr[9], Br[9];
    #pragma unroll
    for (int e = 0; e < 9; e++) {
        const int lo = (dd < e) ? dd : e;
        const int hi = (dd < e) ? e : dd;
        const int tri = lo*9 - (lo*(lo-1))/2 + (hi - lo);
        const double sla_e = G0[45 + e], spr_e = G1[45 + e];
        Cr[e] = G0[tri] - sla_d*sla_e*invM + ((e == dd) ? ALPHA : 0.0);
        Pr[e] = G1[tri] - spr_d*spr_e*invM + ((e == dd) ? ALPHA : 0.0);
        Br[e] = G2[dd*9 + e] - sla_d*spr_e*invM;
    }

    double Lr[9], Dinv[9];
    #pragma unroll
    for (int k = 0; k < 9; k++) {
        const double pkk = __shfl_sync(FULLM, Pr[k], k);
        const double rs  = rsqrt(fmax(pkk, 1e-300));
        const double ldk = Pr[k] * rs;
        Lr[k]   = ldk;
        Dinv[k] = rs;
        #pragma unroll
        for (int j = 0; j < 9; j++)
            if (j > k) Pr[j] -= ldk * __shfl_sync(FULLM, ldk, j);
    }

    double Wr[9];
    #pragma unroll
    for (int e = 0; e < 9; e++) {
        double s = Br[e];
        #pragma unroll
        for (int k = 0; k < 9; k++)
            if (k < e) s -= Wr[k] * __shfl_sync(FULLM, Lr[k], e);
        Wr[e] = s * Dinv[e];
    }

    #pragma unroll
    for (int e = 0; e < 9; e++) {
        double s = 0.0;
        #pragma unroll
        for (int k = 0; k < 9; k++)
            s += Wr[k] * __shfl_sync(FULLM, Wr[k], e);
        Cr[e] -= s;
    }

    double dprod = 1.0;
    #pragma unroll
    for (int k = 0; k < 9; k++) {
        const double akk = __shfl_sync(FULLM, Cr[k], k);
        const double as  = fmax(akk, 1e-300);
        const double rs  = rsqrt(as);
        const double lkk = as * rs;
        dprod *= (lkk + 1e-8);
        const double ldk = Cr[k] * rs;
        #pragma unroll
        for (int j = 0; j < 9; j++)
            if (j > k) Cr[j] -= ldk * __shfl_sync(FULLM, ldk, j);
    }

    if (d == 0) atomicAdd(&g_rmi, log(dprod));
}

// ------------------------- kernel 4: combine --------------------------------
__global__ void k_out(float* __restrict__ outp) {
    const double rmi_total = g_rmi / (double)(N_ * 9);
    const double bce_loss  = g_bce / (g_valid + 1.0);
    outp[0] = (float)(0.5 * bce_loss + 0.5 * rmi_total);
}

// ------------------------- launch ------------------------------------------
extern "C" void kernel_launch(void* const* d_in, const int* in_sizes, int n_in,
                              void* d_out, int out_size) {
    const float* logits = (const float*)d_in[0];
    const void*  labels = d_in[1];

    k_init<<<(GRAMSZ + 255) / 256, 256>>>(labels);
    dim3 g1((PP + 127) / 128, N_);
    k_pool_bce<<<g1, 128>>>(logits, labels);
    dim3 g2(NC, RSPLIT, 4);
    k_gram_all<<<g2, 192>>>();
    k_finalize<<<NC, 32>>>();
    k_out<<<1, 1>>>((float*)d_out);
}

// round 9
// speedup vs baseline: 5.4882x; 1.1824x over previous
#include <cuda_runtime.h>
#include <math.h>
#include <float.h>

#define N_      4
#define C_      21
#define H_      512
#define W_      512
#define HW      (H_*W_)
#define PH      171
#define PP      (PH*PH)      // 29241
#define NH      169
#define M_      (NH*NH)      // 28561
#define NC      (N_*C_)      // 84
#define ALPHA   5e-4
#define CLIPMIN 1e-6f
#define RSPLIT  8
#define ROWCH   ((NH + RSPLIT - 1) / RSPLIT)   // 22
#define GRAMSZ  (NC*3*81)
#define FULLM   0xffffffffu

// ------------------------- device scratch ----------------------------------
// +PH padding: gram kernels prefetch one row beyond the last window row.
__device__ float  g_la[NC*PP + PH];
__device__ float  g_pr[NC*PP + PH];
__device__ double g_gram[GRAMSZ];
__device__ double g_bce;
__device__ double g_valid;
__device__ double g_rmi;
__device__ int    g_lab64;

// ------------------------- kernel 0: zero grams + dtype sniff --------------
__global__ void k_init(const void* lab) {
    const int i = blockIdx.x * blockDim.x + threadIdx.x;
    if (i < GRAMSZ) g_gram[i] = 0.0;
    if (i == 0) {
        const int* p = (const int*)lab;
        bool is64 = true;
        #pragma unroll 1
        for (int k = 0; k < 64; k++)
            if (p[2*k + 1] != 0) { is64 = false; break; }
        g_lab64 = is64 ? 1 : 0;
        g_bce = 0.0; g_valid = 0.0; g_rmi = 0.0;
    }
}

// ------------------------- kernel 1: pool + BCE, smem-staged ---------------
// Block = (pooled row i, batch n). The 3 input rows are staged in shared
// memory with coalesced float4 loads (kills the stride-3 L1 wavefront blowup
// of thread-per-cell gmem access). Cell threads read windows from smem
// (stride 3 = odd stride -> bank-conflict-free).
__global__ void __launch_bounds__(192)
k_pool_bce(const float* __restrict__ logits, const void* __restrict__ labv) {
    const int i   = blockIdx.x;        // pooled row 0..170
    const int n   = blockIdx.y;
    const int tid = threadIdx.x;
    const int y0  = 3*i - 1;

    __shared__ float4 slog4[3][128];
    __shared__ int    slab[3][512];
    float* slog = (float*)slog4;       // [3][512]

    // stage labels for the 3 rows (as validated class or -1)
    {
        const bool is64 = (g_lab64 != 0);
        const long long* L64 = (const long long*)labv;
        const int*       L32 = (const int*)labv;
        #pragma unroll
        for (int k = tid; k < 3*512; k += 192) {
            const int r = k >> 9, x = k & 511;
            const int y = y0 + r;
            int lv = -1;
            if ((unsigned)y < (unsigned)H_) {
                const int gidx = (n*H_ + y)*W_ + x;
                lv = is64 ? (int)L64[gidx] : L32[gidx];
            }
            slab[r][x] = ((unsigned)lv < (unsigned)C_) ? lv : -1;
        }
    }
    __syncthreads();

    // per-cell label metadata (registers, compile-time indexed)
    const int j  = tid;                // cell column
    const int x0 = 3*j - 1;
    int labk[9];
    int xs[3];
    unsigned vmask = 0, labmask = 0;
    int valid = 0;
    if (j < PH) {
        #pragma unroll
        for (int dx = 0; dx < 3; dx++) {
            const int x = x0 + dx;
            xs[dx] = (x < 0) ? 0 : ((x > 511) ? 511 : x);
        }
        #pragma unroll
        for (int s = 0; s < 9; s++) {
            const int x = x0 + (s % 3);
            const bool inb = ((unsigned)x < (unsigned)W_);
            const int lv = inb ? slab[s/3][x] : -1;
            labk[s] = lv;
            if (lv >= 0) { vmask |= (1u << s); valid++; labmask |= (1u << lv); }
        }
    }

    float bce_acc = 0.f;
    const int ncbase = n * C_;
    const int cell   = i*PH + j;

    #pragma unroll 1
    for (int c = 0; c < C_; c++) {
        __syncthreads();   // previous class compute done before overwrite
        // stage 3 logit rows, coalesced float4
        {
            const float* __restrict__ src = logits + (size_t)(ncbase + c) * HW;
            #pragma unroll
            for (int k = tid; k < 3*128; k += 192) {
                const int r = k >> 7, q = k & 127;
                const int y = y0 + r;
                float4 v = make_float4(0.f, 0.f, 0.f, 0.f);
                if ((unsigned)y < (unsigned)H_)
                    v = *(const float4*)(src + y*W_ + 4*q);
                slog4[r][q] = v;
            }
        }
        __syncthreads();

        if (j < PH) {
            float maxv = -FLT_MAX;
            float prod = 1.f;          // prod over valid pixels of (1+e^{-|x|})
            float racc = 0.f;          // sum relu(x) - onehot*x
            #pragma unroll
            for (int s = 0; s < 9; s++) {
                float xv = slog[(s/3)*512 + xs[s % 3]];
                xv = ((vmask >> s) & 1u) ? xv : -FLT_MAX;
                maxv = fmaxf(maxv, xv);
                const float t = __expf(-fabsf(xv));
                prod = fmaf(prod, t, prod);
                racc += fmaxf(xv, 0.f);
                racc -= (labk[s] == c) ? xv : 0.f;
            }
            bce_acc += racc + __logf(prod);
            const float t = __expf(-fabsf(maxv));
            const float u = __fdividef(1.f, 1.f + t);
            const float sg = (maxv >= 0.f) ? u : t * u;
            g_pr[(ncbase + c)*PP + cell] = sg + CLIPMIN;
            g_la[(ncbase + c)*PP + cell] = ((labmask >> c) & 1u) ? 1.f : 0.f;
        }
    }

    // block reduce -> atomic
    double b = (double)bce_acc, v = (double)valid;
    #pragma unroll
    for (int o = 16; o > 0; o >>= 1) {
        b += __shfl_down_sync(FULLM, b, o);
        v += __shfl_down_sync(FULLM, v, o);
    }
    __shared__ double sb[6], sv[6];
    const int lane = tid & 31, wid = tid >> 5;
    if (lane == 0) { sb[wid] = b; sv[wid] = v; }
    __syncthreads();
    if (tid == 0) {
        double tb = 0, tv = 0;
        #pragma unroll
        for (int w = 0; w < 6; w++) { tb += sb[w]; tv += sv[w]; }
        atomicAdd(&g_bce, tb);
        atomicAdd(&g_valid, tv);
    }
}

// ------------------------- gram bodies (R8, unchanged) ---------------------
__device__ __forceinline__ void self_body(const float* __restrict__ A0,
                                          int i0, int i1,
                                          double* __restrict__ out, int j) {
    float acc[54];
    #pragma unroll
    for (int k = 0; k < 54; k++) acc[k] = 0.f;

    if (j < NH) {
        const float* __restrict__ A = A0 + i0*PH + j;
        float w0[3], w1[3], nxt[3];
        #pragma unroll
        for (int c = 0; c < 3; c++) w0[c] = A[c];
        A += PH;
        #pragma unroll
        for (int c = 0; c < 3; c++) w1[c] = A[c];
        A += PH;
        #pragma unroll
        for (int c = 0; c < 3; c++) nxt[c] = A[c];
        A += PH;

        #pragma unroll 2
        for (int i = i0; i < i1; i++) {
            float a[9] = { w0[0], w0[1], w0[2],
                           w1[0], w1[1], w1[2],
                           nxt[0], nxt[1], nxt[2] };
            #pragma unroll
            for (int c = 0; c < 3; c++) nxt[c] = A[c];
            A += PH;

            int k = 0;
            #pragma unroll
            for (int d = 0; d < 9; d++)
                #pragma unroll
                for (int e = d; e < 9; e++)
                    acc[k++] += a[d] * a[e];
            #pragma unroll
            for (int d = 0; d < 9; d++) acc[45 + d] += a[d];

            #pragma unroll
            for (int c = 0; c < 3; c++) { w0[c] = w1[c]; w1[c] = a[6 + c]; }
        }
    }

    const int lane = threadIdx.x & 31;
    #pragma unroll
    for (int k = 0; k < 54; k++) {
        float x = acc[k];
        #pragma unroll
        for (int o = 16; o > 0; o >>= 1) x += __shfl_xor_sync(FULLM, x, o);
        if (lane == (k & 31)) atomicAdd(&out[k], (double)x);
    }
}

template<int EL, int NE>
__device__ __forceinline__ void cross_body(const float* __restrict__ Ab,
                                           const float* __restrict__ Bb,
                                           int i0, int i1,
                                           double* __restrict__ out, int j) {
    float acc[9*NE];
    #pragma unroll
    for (int k = 0; k < 9*NE; k++) acc[k] = 0.f;

    if (j < NH) {
        const float* __restrict__ A = Ab + i0*PH + j;
        const float* __restrict__ B = Bb + i0*PH + j;
        float wa0[3], wa1[3], na[3];
        float wb0[3], wb1[3], nb[3];
        #pragma unroll
        for (int c = 0; c < 3; c++) { wa0[c] = A[c]; wb0[c] = B[c]; }
        A += PH; B += PH;
        #pragma unroll
        for (int c = 0; c < 3; c++) { wa1[c] = A[c]; wb1[c] = B[c]; }
        A += PH; B += PH;
        #pragma unroll
        for (int c = 0; c < 3; c++) { na[c] = A[c]; nb[c] = B[c]; }
        A += PH; B += PH;

        #pragma unroll 2
        for (int i = i0; i < i1; i++) {
            float a[9] = { wa0[0], wa0[1], wa0[2],
                           wa1[0], wa1[1], wa1[2],
                           na[0],  na[1],  na[2] };
            float b[9] = { wb0[0], wb0[1], wb0[2],
                           wb1[0], wb1[1], wb1[2],
                           nb[0],  nb[1],  nb[2] };
            #pragma unroll
            for (int c = 0; c < 3; c++) { na[c] = A[c]; nb[c] = B[c]; }
            A += PH; B += PH;

            #pragma unroll
            for (int d = 0; d < 9; d++)
                #pragma unroll
                for (int e = 0; e < NE; e++)
                    acc[d*NE + e] += a[d] * b[EL + e];

            #pragma unroll
            for (int c = 0; c < 3; c++) {
                wa0[c] = wa1[c]; wa1[c] = a[6 + c];
                wb0[c] = wb1[c]; wb1[c] = b[6 + c];
            }
        }
    }

    const int lane = threadIdx.x & 31;
    #pragma unroll
    for (int k = 0; k < 9*NE; k++) {
        float x = acc[k];
        #pragma unroll
        for (int o = 16; o > 0; o >>= 1) x += __shfl_xor_sync(FULLM, x, o);
        const int d = k / NE, e = EL + (k % NE);
        if (lane == (k & 31)) atomicAdd(&out[d*9 + e], (double)x);
    }
}

// ------------------------- kernel 2: all Grams, one launch -----------------
__global__ void __launch_bounds__(192)
k_gram_all() {
    const int nc = blockIdx.x;
    const int z  = blockIdx.z;
    const int j  = threadIdx.x;
    const int i0 = blockIdx.y * ROWCH;
    const int i1 = (i0 + ROWCH < NH) ? (i0 + ROWCH) : NH;
    const size_t base = (size_t)nc * PP;
    double* __restrict__ out = g_gram + (size_t)(nc*3) * 81;

    if (z == 0)      self_body(g_la + base, i0, i1, out, j);
    else if (z == 1) self_body(g_pr + base, i0, i1, out + 81, j);
    else if (z == 2) cross_body<0,5>(g_la + base, g_pr + base, i0, i1, out + 162, j);
    else             cross_body<5,4>(g_la + base, g_pr + base, i0, i1, out + 162, j);
}

// ------------------------- kernel 3: linear algebra, fp32 chains -----------
// Covariance assembly (cancellation-sensitive) stays fp64; the serial
// Cholesky / solve chains run in fp32 (matching the fp32 reference),
// cutting chain latency ~6x (FFMA lat 4 vs DFMA 47, MUFU rsqrt).
__global__ void __launch_bounds__(32)
k_finalize() {
    const int nc = blockIdx.x;
    const int d  = threadIdx.x;
    const int dd = (d < 9) ? d : 0;

    const double* __restrict__ G0 = g_gram + (size_t)(nc*3 + 0)*81;
    const double* __restrict__ G1 = g_gram + (size_t)(nc*3 + 1)*81;
    const double* __restrict__ G2 = g_gram + (size_t)(nc*3 + 2)*81;

    const double invM = 1.0 / (double)M_;
    const double sla_d = G0[45 + dd], spr_d = G1[45 + dd];

    float Cr[9], Pr[9], Br[9];
    #pragma unroll
    for (int e = 0; e < 9; e++) {
        const int lo = (dd < e) ? dd : e;
        const int hi = (dd < e) ? e : dd;
        const int tri = lo*9 - (lo*(lo-1))/2 + (hi - lo);
        const double sla_e = G0[45 + e], spr_e = G1[45 + e];
        Cr[e] = (float)(G0[tri] - sla_d*sla_e*invM + ((e == dd) ? ALPHA : 0.0));
        Pr[e] = (float)(G1[tri] - spr_d*spr_e*invM + ((e == dd) ? ALPHA : 0.0));
        Br[e] = (float)(G2[dd*9 + e] - sla_d*spr_e*invM);
    }

    // Cholesky of P; lane d ends with Lr[k]=L[d][k]; Dinv[k]=1/L[k][k].
    float Lr[9], Dinv[9];
    #pragma unroll
    for (int k = 0; k < 9; k++) {
        const float pkk = __shfl_sync(FULLM, Pr[k], k);
        const float rs  = rsqrtf(fmaxf(pkk, 1e-30f));
        const float ldk = Pr[k] * rs;
        Lr[k]   = ldk;
        Dinv[k] = rs;
        #pragma unroll
        for (int j = 0; j < 9; j++)
            if (j > k) Pr[j] -= ldk * __shfl_sync(FULLM, ldk, j);
    }

    // W = B L^{-T}
    float Wr[9];
    #pragma unroll
    for (int e = 0; e < 9; e++) {
        float s = Br[e];
        #pragma unroll
        for (int k = 0; k < 9; k++)
            if (k < e) s -= Wr[k] * __shfl_sync(FULLM, Lr[k], e);
        Wr[e] = s * Dinv[e];
    }

    // A2 = Cla + alpha I - W W^T
    #pragma unroll
    for (int e = 0; e < 9; e++) {
        float s = 0.f;
        #pragma unroll
        for (int k = 0; k < 9; k++)
            s += Wr[k] * __shfl_sync(FULLM, Wr[k], e);
        Cr[e] -= s;
    }

    // Cholesky of A2; product of (diag + 1e-8), single log.
    float dprod = 1.f;
    #pragma unroll
    for (int k = 0; k < 9; k++) {
        const float akk = __shfl_sync(FULLM, Cr[k], k);
        const float as  = fmaxf(akk, 1e-30f);
        const float rs  = rsqrtf(as);
        const float lkk = as * rs;
        dprod *= (lkk + 1e-8f);
        const float ldk = Cr[k] * rs;
        #pragma unroll
        for (int j = 0; j < 9; j++)
            if (j > k) Cr[j] -= ldk * __shfl_sync(FULLM, ldk, j);
    }

    if (d == 0) atomicAdd(&g_rmi, (double)logf(dprod));
}

// ------------------------- kernel 4: combine --------------------------------
__global__ void k_out(float* __restrict__ outp) {
    const double rmi_total = g_rmi / (double)(N_ * 9);
    const double bce_loss  = g_bce / (g_valid + 1.0);
    outp[0] = (float)(0.5 * bce_loss + 0.5 * rmi_total);
}

// ------------------------- launch ------------------------------------------
extern "C" void kernel_launch(void* const* d_in, const int* in_sizes, int n_in,
                              void* d_out, int out_size) {
    const float* logits = (const float*)d_in[0];
    const void*  labels = d_in[1];

    k_init<<<(GRAMSZ + 255) / 256, 256>>>(labels);
    dim3 gp(PH, N_);
    k_pool_bce<<<gp, 192>>>(logits, labels);
    dim3 g2(NC, RSPLIT, 4);
    k_gram_all<<<g2, 192>>>();
    k_finalize<<<NC, 32>>>();
    k_out<<<1, 1>>>((float*)d_out);
}

// round 10
// speedup vs baseline: 7.4621x; 1.3596x over previous
#include <cuda_runtime.h>
#include <math.h>
#include <float.h>

#define N_      4
#define C_      21
#define H_      512
#define W_      512
#define HW      (H_*W_)
#define PH      171
#define PP      (PH*PH)      // 29241
#define NH      169
#define M_      (NH*NH)      // 28561
#define NC      (N_*C_)      // 84
#define ALPHA   5e-4
#define CLIPMIN 1e-6f
#define RSPLIT  7
#define ROWCH   ((NH + RSPLIT - 1) / RSPLIT)   // 25
#define GRAMSZ  (NC*3*81)
#define FULLM   0xffffffffu

// ------------------------- device scratch ----------------------------------
// +PH padding: gram kernels prefetch one row beyond the last window row.
__device__ float  g_la[NC*PP + PH];
__device__ float  g_pr[NC*PP + PH];
__device__ double g_gram[GRAMSZ];
__device__ double g_bce;
__device__ double g_valid;
__device__ double g_rmi;
__device__ int    g_lab64;

// ------------------------- kernel 0: zero grams + dtype sniff --------------
__global__ void k_init(const void* lab) {
    const int i = blockIdx.x * blockDim.x + threadIdx.x;
    if (i < GRAMSZ) g_gram[i] = 0.0;
    if (i == 0) {
        const int* p = (const int*)lab;
        bool is64 = true;
        #pragma unroll 1
        for (int k = 0; k < 64; k++)
            if (p[2*k + 1] != 0) { is64 = false; break; }
        g_lab64 = is64 ? 1 : 0;
        g_bce = 0.0; g_valid = 0.0; g_rmi = 0.0;
    }
}

// ------------------------- kernel 1: pool + BCE, smem-staged (R9) ----------
__global__ void __launch_bounds__(192)
k_pool_bce(const float* __restrict__ logits, const void* __restrict__ labv) {
    const int i   = blockIdx.x;        // pooled row 0..170
    const int n   = blockIdx.y;
    const int tid = threadIdx.x;
    const int y0  = 3*i - 1;

    __shared__ float4 slog4[3][128];
    __shared__ int    slab[3][512];
    float* slog = (float*)slog4;       // [3][512]

    {
        const bool is64 = (g_lab64 != 0);
        const long long* L64 = (const long long*)labv;
        const int*       L32 = (const int*)labv;
        #pragma unroll
        for (int k = tid; k < 3*512; k += 192) {
            const int r = k >> 9, x = k & 511;
            const int y = y0 + r;
            int lv = -1;
            if ((unsigned)y < (unsigned)H_) {
                const int gidx = (n*H_ + y)*W_ + x;
                lv = is64 ? (int)L64[gidx] : L32[gidx];
            }
            slab[r][x] = ((unsigned)lv < (unsigned)C_) ? lv : -1;
        }
    }
    __syncthreads();

    const int j  = tid;                // cell column
    const int x0 = 3*j - 1;
    int labk[9];
    int xs[3];
    unsigned vmask = 0, labmask = 0;
    int valid = 0;
    if (j < PH) {
        #pragma unroll
        for (int dx = 0; dx < 3; dx++) {
            const int x = x0 + dx;
            xs[dx] = (x < 0) ? 0 : ((x > 511) ? 511 : x);
        }
        #pragma unroll
        for (int s = 0; s < 9; s++) {
            const int x = x0 + (s % 3);
            const bool inb = ((unsigned)x < (unsigned)W_);
            const int lv = inb ? slab[s/3][x] : -1;
            labk[s] = lv;
            if (lv >= 0) { vmask |= (1u << s); valid++; labmask |= (1u << lv); }
        }
    }

    float bce_acc = 0.f;
    const int ncbase = n * C_;
    const int cell   = i*PH + j;

    #pragma unroll 1
    for (int c = 0; c < C_; c++) {
        __syncthreads();
        {
            const float* __restrict__ src = logits + (size_t)(ncbase + c) * HW;
            #pragma unroll
            for (int k = tid; k < 3*128; k += 192) {
                const int r = k >> 7, q = k & 127;
                const int y = y0 + r;
                float4 v = make_float4(0.f, 0.f, 0.f, 0.f);
                if ((unsigned)y < (unsigned)H_)
                    v = *(const float4*)(src + y*W_ + 4*q);
                slog4[r][q] = v;
            }
        }
        __syncthreads();

        if (j < PH) {
            float maxv = -FLT_MAX;
            float prod = 1.f;
            float racc = 0.f;
            #pragma unroll
            for (int s = 0; s < 9; s++) {
                float xv = slog[(s/3)*512 + xs[s % 3]];
                xv = ((vmask >> s) & 1u) ? xv : -FLT_MAX;
                maxv = fmaxf(maxv, xv);
                const float t = __expf(-fabsf(xv));
                prod = fmaf(prod, t, prod);
                racc += fmaxf(xv, 0.f);
                racc -= (labk[s] == c) ? xv : 0.f;
            }
            bce_acc += racc + __logf(prod);
            const float t = __expf(-fabsf(maxv));
            const float u = __fdividef(1.f, 1.f + t);
            const float sg = (maxv >= 0.f) ? u : t * u;
            g_pr[(ncbase + c)*PP + cell] = sg + CLIPMIN;
            g_la[(ncbase + c)*PP + cell] = ((labmask >> c) & 1u) ? 1.f : 0.f;
        }
    }

    double b = (double)bce_acc, v = (double)valid;
    #pragma unroll
    for (int o = 16; o > 0; o >>= 1) {
        b += __shfl_down_sync(FULLM, b, o);
        v += __shfl_down_sync(FULLM, v, o);
    }
    __shared__ double sb[6], sv[6];
    const int lane = tid & 31, wid = tid >> 5;
    if (lane == 0) { sb[wid] = b; sv[wid] = v; }
    __syncthreads();
    if (tid == 0) {
        double tb = 0, tv = 0;
        #pragma unroll
        for (int w = 0; w < 6; w++) { tb += sb[w]; tv += sv[w]; }
        atomicAdd(&g_bce, tb);
        atomicAdd(&g_valid, tv);
    }
}

// ------------------------- gram epilogue: block reduce, few atomics --------
// Butterfly per warp -> smem -> one thread per entry does the single atomic.
// 6x fewer global atomics than per-warp atomics.
template<int NACC>
__device__ __forceinline__ void block_reduce(const float* acc,
                                             float (*sred)[54],
                                             float* outv /*size NACC*/) {
    const int lane = threadIdx.x & 31, wid = threadIdx.x >> 5;
    #pragma unroll
    for (int k = 0; k < NACC; k++) {
        float x = acc[k];
        #pragma unroll
        for (int o = 16; o > 0; o >>= 1) x += __shfl_xor_sync(FULLM, x, o);
        if (lane == 0) sred[wid][k] = x;
    }
    __syncthreads();
    if (threadIdx.x < NACC) {
        float s = 0.f;
        #pragma unroll
        for (int w = 0; w < 6; w++) s += sred[w][threadIdx.x];
        outv[threadIdx.x] = s;
    }
}

// ------------------------- gram bodies -------------------------------------
__device__ __forceinline__ void self_body(const float* __restrict__ A0,
                                          int i0, int i1,
                                          double* __restrict__ out, int j,
                                          float (*sred)[54]) {
    float acc[54];
    #pragma unroll
    for (int k = 0; k < 54; k++) acc[k] = 0.f;

    if (j < NH) {
        const float* __restrict__ A = A0 + i0*PH + j;
        float w0[3], w1[3], nxt[3];
        #pragma unroll
        for (int c = 0; c < 3; c++) w0[c] = A[c];
        A += PH;
        #pragma unroll
        for (int c = 0; c < 3; c++) w1[c] = A[c];
        A += PH;
        #pragma unroll
        for (int c = 0; c < 3; c++) nxt[c] = A[c];
        A += PH;

        #pragma unroll 2
        for (int i = i0; i < i1; i++) {
            float a[9] = { w0[0], w0[1], w0[2],
                           w1[0], w1[1], w1[2],
                           nxt[0], nxt[1], nxt[2] };
            #pragma unroll
            for (int c = 0; c < 3; c++) nxt[c] = A[c];
            A += PH;

            int k = 0;
            #pragma unroll
            for (int d = 0; d < 9; d++)
                #pragma unroll
                for (int e = d; e < 9; e++)
                    acc[k++] += a[d] * a[e];
            #pragma unroll
            for (int d = 0; d < 9; d++) acc[45 + d] += a[d];

            #pragma unroll
            for (int c = 0; c < 3; c++) { w0[c] = w1[c]; w1[c] = a[6 + c]; }
        }
    }

    float red[1];  // reuse pattern: block_reduce writes into a local then atomic
    (void)red;
    __shared__ float outv[54];
    block_reduce<54>(acc, sred, outv);
    if (threadIdx.x < 54) atomicAdd(&out[threadIdx.x], (double)outv[threadIdx.x]);
}

template<int EL, int NE>
__device__ __forceinline__ void cross_body(const float* __restrict__ Ab,
                                           const float* __restrict__ Bb,
                                           int i0, int i1,
                                           double* __restrict__ out, int j,
                                           float (*sred)[54]) {
    float acc[9*NE];
    #pragma unroll
    for (int k = 0; k < 9*NE; k++) acc[k] = 0.f;

    if (j < NH) {
        const float* __restrict__ A = Ab + i0*PH + j;
        const float* __restrict__ B = Bb + i0*PH + j;
        float wa0[3], wa1[3], na[3];
        float wb0[3], wb1[3], nb[3];
        #pragma unroll
        for (int c = 0; c < 3; c++) { wa0[c] = A[c]; wb0[c] = B[c]; }
        A += PH; B += PH;
        #pragma unroll
        for (int c = 0; c < 3; c++) { wa1[c] = A[c]; wb1[c] = B[c]; }
        A += PH; B += PH;
        #pragma unroll
        for (int c = 0; c < 3; c++) { na[c] = A[c]; nb[c] = B[c]; }
        A += PH; B += PH;

        #pragma unroll 2
        for (int i = i0; i < i1; i++) {
            float a[9] = { wa0[0], wa0[1], wa0[2],
                           wa1[0], wa1[1], wa1[2],
                           na[0],  na[1],  na[2] };
            float b[9] = { wb0[0], wb0[1], wb0[2],
                           wb1[0], wb1[1], wb1[2],
                           nb[0],  nb[1],  nb[2] };
            #pragma unroll
            for (int c = 0; c < 3; c++) { na[c] = A[c]; nb[c] = B[c]; }
            A += PH; B += PH;

            #pragma unroll
            for (int d = 0; d < 9; d++)
                #pragma unroll
                for (int e = 0; e < NE; e++)
                    acc[d*NE + e] += a[d] * b[EL + e];

            #pragma unroll
            for (int c = 0; c < 3; c++) {
                wa0[c] = wa1[c]; wa1[c] = a[6 + c];
                wb0[c] = wb1[c]; wb1[c] = b[6 + c];
            }
        }
    }

    __shared__ float outv[54];
    block_reduce<9*NE>(acc, sred, outv);
    if (threadIdx.x < 9*NE) {
        const int d = threadIdx.x / NE, e = EL + (threadIdx.x % NE);
        atomicAdd(&out[d*9 + e], (double)outv[threadIdx.x]);
    }
}

// ------------------------- kernel 2: all Grams, one launch -----------------
// blockIdx.z: 0 la-self, 1 pr-self, 2 cross e[0,5), 3 cross e[5,9)
__global__ void __launch_bounds__(192)
k_gram_all() {
    __shared__ float sred[6][54];
    const int nc = blockIdx.x;
    const int z  = blockIdx.z;
    const int j  = threadIdx.x;
    const int i0 = blockIdx.y * ROWCH;
    const int i1 = (i0 + ROWCH < NH) ? (i0 + ROWCH) : NH;
    const size_t base = (size_t)nc * PP;
    double* __restrict__ out = g_gram + (size_t)(nc*3) * 81;

    if (z == 0)      self_body(g_la + base, i0, i1, out, j, sred);
    else if (z == 1) self_body(g_pr + base, i0, i1, out + 81, j, sred);
    else if (z == 2) cross_body<0,5>(g_la + base, g_pr + base, i0, i1, out + 162, j, sred);
    else             cross_body<5,4>(g_la + base, g_pr + base, i0, i1, out + 162, j, sred);
}

// ------------------------- kernel 3: linear algebra, fp32 chains (R9) ------
__global__ void __launch_bounds__(32)
k_finalize() {
    const int nc = blockIdx.x;
    const int d  = threadIdx.x;
    const int dd = (d < 9) ? d : 0;

    const double* __restrict__ G0 = g_gram + (size_t)(nc*3 + 0)*81;
    const double* __restrict__ G1 = g_gram + (size_t)(nc*3 + 1)*81;
    const double* __restrict__ G2 = g_gram + (size_t)(nc*3 + 2)*81;

    const double invM = 1.0 / (double)M_;
    const double sla_d = G0[45 + dd], spr_d = G1[45 + dd];

    float Cr[9], Pr[9], Br[9];
    #pragma unroll
    for (int e = 0; e < 9; e++) {
        const int lo = (dd < e) ? dd : e;
        const int hi = (dd < e) ? e : dd;
        const int tri = lo*9 - (lo*(lo-1))/2 + (hi - lo);
        const double sla_e = G0[45 + e], spr_e = G1[45 + e];
        Cr[e] = (float)(G0[tri] - sla_d*sla_e*invM + ((e == dd) ? ALPHA : 0.0));
        Pr[e] = (float)(G1[tri] - spr_d*spr_e*invM + ((e == dd) ? ALPHA : 0.0));
        Br[e] = (float)(G2[dd*9 + e] - sla_d*spr_e*invM);
    }

    float Lr[9], Dinv[9];
    #pragma unroll
    for (int k = 0; k < 9; k++) {
        const float pkk = __shfl_sync(FULLM, Pr[k], k);
        const float rs  = rsqrtf(fmaxf(pkk, 1e-30f));
        const float ldk = Pr[k] * rs;
        Lr[k]   = ldk;
        Dinv[k] = rs;
        #pragma unroll
        for (int j = 0; j < 9; j++)
            if (j > k) Pr[j] -= ldk * __shfl_sync(FULLM, ldk, j);
    }

    float Wr[9];
    #pragma unroll
    for (int e = 0; e < 9; e++) {
        float s = Br[e];
        #pragma unroll
        for (int k = 0; k < 9; k++)
            if (k < e) s -= Wr[k] * __shfl_sync(FULLM, Lr[k], e);
        Wr[e] = s * Dinv[e];
    }

    #pragma unroll
    for (int e = 0; e < 9; e++) {
        float s = 0.f;
        #pragma unroll
        for (int k = 0; k < 9; k++)
            s += Wr[k] * __shfl_sync(FULLM, Wr[k], e);
        Cr[e] -= s;
    }

    float dprod = 1.f;
    #pragma unroll
    for (int k = 0; k < 9; k++) {
        const float akk = __shfl_sync(FULLM, Cr[k], k);
        const float as  = fmaxf(akk, 1e-30f);
        const float rs  = rsqrtf(as);
        const float lkk = as * rs;
        dprod *= (lkk + 1e-8f);
        const float ldk = Cr[k] * rs;
        #pragma unroll
        for (int j = 0; j < 9; j++)
            if (j > k) Cr[j] -= ldk * __shfl_sync(FULLM, ldk, j);
    }

    if (d == 0) atomicAdd(&g_rmi, (double)logf(dprod));
}

// ------------------------- kernel 4: combine --------------------------------
__global__ void k_out(float* __restrict__ outp) {
    const double rmi_total = g_rmi / (double)(N_ * 9);
    const double bce_loss  = g_bce / (g_valid + 1.0);
    outp[0] = (float)(0.5 * bce_loss + 0.5 * rmi_total);
}

// ------------------------- launch ------------------------------------------
extern "C" void kernel_launch(void* const* d_in, const int* in_sizes, int n_in,
                              void* d_out, int out_size) {
    const float* logits = (const float*)d_in[0];
    const void*  labels = d_in[1];

    k_init<<<(GRAMSZ + 255) / 256, 256>>>(labels);
    dim3 gp(PH, N_);
    k_pool_bce<<<gp, 192>>>(logits, labels);
    dim3 g2(NC, RSPLIT, 4);
    k_gram_all<<<g2, 192>>>();
    k_finalize<<<NC, 32>>>();
    k_out<<<1, 1>>>((float*)d_out);
}

// round 11
// speedup vs baseline: 7.4996x; 1.0050x over previous
#include <cuda_runtime.h>
#include <math.h>
#include <float.h>

#define N_      4
#define C_      21
#define H_      512
#define W_      512
#define HW      (H_*W_)
#define PH      171
#define PP      (PH*PH)      // 29241
#define NH      169
#define M_      (NH*NH)      // 28561
#define NC      (N_*C_)      // 84
#define ALPHA   5e-4
#define CLIPMIN 1e-6f
#define RSPLIT  7
#define ROWCH   ((NH + RSPLIT - 1) / RSPLIT)   // 25
#define GRAMSZ  (NC*3*81)
#define FULLM   0xffffffffu

// ------------------------- device scratch ----------------------------------
// +PH padding: gram kernels prefetch one row beyond the last window row.
__device__ float  g_la[NC*PP + PH];
__device__ float  g_pr[NC*PP + PH];
__device__ double g_gram[GRAMSZ];
__device__ double g_bce;
__device__ double g_valid;
__device__ double g_rmi;
__device__ int    g_lab64;
__device__ int    g_done;

// ------------------------- kernel 0: zero grams + dtype sniff --------------
__global__ void k_init(const void* lab) {
    const int i = blockIdx.x * blockDim.x + threadIdx.x;
    if (i < GRAMSZ) g_gram[i] = 0.0;
    if (i == 0) {
        const int* p = (const int*)lab;
        bool is64 = true;
        #pragma unroll 1
        for (int k = 0; k < 64; k++)
            if (p[2*k + 1] != 0) { is64 = false; break; }
        g_lab64 = is64 ? 1 : 0;
        g_bce = 0.0; g_valid = 0.0; g_rmi = 0.0; g_done = 0;
    }
}

// ------------------------- kernel 1: pool + BCE, double-buffered smem ------
// Block = (pooled row i, batch n). Class c+1's 3 input rows stream into the
// ping-pong smem buffer while class c computes: one sync per class, loads
// hidden under the exp/log math.
__global__ void __launch_bounds__(192)
k_pool_bce(const float* __restrict__ logits, const void* __restrict__ labv) {
    const int i   = blockIdx.x;        // pooled row 0..170
    const int n   = blockIdx.y;
    const int tid = threadIdx.x;
    const int y0  = 3*i - 1;

    __shared__ float4 slog4[2][3][128];
    __shared__ int    slab[3][512];

    // stage labels for the 3 rows (validated class or -1)
    {
        const bool is64 = (g_lab64 != 0);
        const long long* L64 = (const long long*)labv;
        const int*       L32 = (const int*)labv;
        #pragma unroll
        for (int k = tid; k < 3*512; k += 192) {
            const int r = k >> 9, x = k & 511;
            const int y = y0 + r;
            int lv = -1;
            if ((unsigned)y < (unsigned)H_) {
                const int gidx = (n*H_ + y)*W_ + x;
                lv = is64 ? (int)L64[gidx] : L32[gidx];
            }
            slab[r][x] = ((unsigned)lv < (unsigned)C_) ? lv : -1;
        }
    }

    const int ncbase = n * C_;
    const float* __restrict__ lbase = logits + (size_t)ncbase * HW;

    // stage helper rows for class c into buffer b (coalesced float4)
    auto stage = [&](int b, int c) {
        const float* __restrict__ src = lbase + (size_t)c * HW;
        #pragma unroll
        for (int k = tid; k < 3*128; k += 192) {
            const int r = k >> 7, q = k & 127;
            const int y = y0 + r;
            float4 v = make_float4(0.f, 0.f, 0.f, 0.f);
            if ((unsigned)y < (unsigned)H_)
                v = *(const float4*)(src + y*W_ + 4*q);
            slog4[b][r][q] = v;
        }
    };

    stage(0, 0);
    __syncthreads();   // labels + class-0 rows ready

    // per-cell label metadata (registers, compile-time indexed)
    const int j  = tid;                // cell column
    const int x0 = 3*j - 1;
    int labk[9];
    int xs[3];
    unsigned vmask = 0, labmask = 0;
    int valid = 0;
    if (j < PH) {
        #pragma unroll
        for (int dx = 0; dx < 3; dx++) {
            const int x = x0 + dx;
            xs[dx] = (x < 0) ? 0 : ((x > 511) ? 511 : x);
        }
        #pragma unroll
        for (int s = 0; s < 9; s++) {
            const int x = x0 + (s % 3);
            const bool inb = ((unsigned)x < (unsigned)W_);
            const int lv = inb ? slab[s/3][x] : -1;
            labk[s] = lv;
            if (lv >= 0) { vmask |= (1u << s); valid++; labmask |= (1u << lv); }
        }
    }

    float bce_acc = 0.f;
    const int cell = i*PH + j;

    #pragma unroll 1
    for (int c = 0; c < C_; c++) {
        const int b = c & 1;
        if (c + 1 < C_) stage(1 - b, c + 1);   // prefetch next class

        if (j < PH) {
            const float* slog = (const float*)slog4[b];   // [3][512]
            float maxv = -FLT_MAX;
            float prod = 1.f;          // prod over valid pixels of (1+e^{-|x|})
            float racc = 0.f;          // sum relu(x) - onehot*x
            #pragma unroll
            for (int s = 0; s < 9; s++) {
                float xv = slog[(s/3)*512 + xs[s % 3]];
                xv = ((vmask >> s) & 1u) ? xv : -FLT_MAX;
                maxv = fmaxf(maxv, xv);
                const float t = __expf(-fabsf(xv));
                prod = fmaf(prod, t, prod);
                racc += fmaxf(xv, 0.f);
                racc -= (labk[s] == c) ? xv : 0.f;
            }
            bce_acc += racc + __logf(prod);
            const float t = __expf(-fabsf(maxv));
            const float u = __fdividef(1.f, 1.f + t);
            const float sg = (maxv >= 0.f) ? u : t * u;
            g_pr[(ncbase + c)*PP + cell] = sg + CLIPMIN;
            g_la[(ncbase + c)*PP + cell] = ((labmask >> c) & 1u) ? 1.f : 0.f;
        }
        __syncthreads();   // next buffer staged AND this buffer's compute done
    }

    // block reduce -> atomic
    double b = (double)bce_acc, v = (double)valid;
    #pragma unroll
    for (int o = 16; o > 0; o >>= 1) {
        b += __shfl_down_sync(FULLM, b, o);
        v += __shfl_down_sync(FULLM, v, o);
    }
    __shared__ double sb[6], sv[6];
    const int lane = tid & 31, wid = tid >> 5;
    if (lane == 0) { sb[wid] = b; sv[wid] = v; }
    __syncthreads();
    if (tid == 0) {
        double tb = 0, tv = 0;
        #pragma unroll
        for (int w = 0; w < 6; w++) { tb += sb[w]; tv += sv[w]; }
        atomicAdd(&g_bce, tb);
        atomicAdd(&g_valid, tv);
    }
}

// ------------------------- gram epilogue: block reduce, few atomics --------
template<int NACC>
__device__ __forceinline__ void block_reduce(const float* acc,
                                             float (*sred)[54],
                                             float* outv /*size NACC*/) {
    const int lane = threadIdx.x & 31, wid = threadIdx.x >> 5;
    #pragma unroll
    for (int k = 0; k < NACC; k++) {
        float x = acc[k];
        #pragma unroll
        for (int o = 16; o > 0; o >>= 1) x += __shfl_xor_sync(FULLM, x, o);
        if (lane == 0) sred[wid][k] = x;
    }
    __syncthreads();
    if (threadIdx.x < NACC) {
        float s = 0.f;
        #pragma unroll
        for (int w = 0; w < 6; w++) s += sred[w][threadIdx.x];
        outv[threadIdx.x] = s;
    }
}

// ------------------------- gram bodies (R10, unchanged) --------------------
__device__ __forceinline__ void self_body(const float* __restrict__ A0,
                                          int i0, int i1,
                                          double* __restrict__ out, int j,
                                          float (*sred)[54]) {
    float acc[54];
    #pragma unroll
    for (int k = 0; k < 54; k++) acc[k] = 0.f;

    if (j < NH) {
        const float* __restrict__ A = A0 + i0*PH + j;
        float w0[3], w1[3], nxt[3];
        #pragma unroll
        for (int c = 0; c < 3; c++) w0[c] = A[c];
        A += PH;
        #pragma unroll
        for (int c = 0; c < 3; c++) w1[c] = A[c];
        A += PH;
        #pragma unroll
        for (int c = 0; c < 3; c++) nxt[c] = A[c];
        A += PH;

        #pragma unroll 2
        for (int i = i0; i < i1; i++) {
            float a[9] = { w0[0], w0[1], w0[2],
                           w1[0], w1[1], w1[2],
                           nxt[0], nxt[1], nxt[2] };
            #pragma unroll
            for (int c = 0; c < 3; c++) nxt[c] = A[c];
            A += PH;

            int k = 0;
            #pragma unroll
            for (int d = 0; d < 9; d++)
                #pragma unroll
                for (int e = d; e < 9; e++)
                    acc[k++] += a[d] * a[e];
            #pragma unroll
            for (int d = 0; d < 9; d++) acc[45 + d] += a[d];

            #pragma unroll
            for (int c = 0; c < 3; c++) { w0[c] = w1[c]; w1[c] = a[6 + c]; }
        }
    }

    __shared__ float outv[54];
    block_reduce<54>(acc, sred, outv);
    if (threadIdx.x < 54) atomicAdd(&out[threadIdx.x], (double)outv[threadIdx.x]);
}

template<int EL, int NE>
__device__ __forceinline__ void cross_body(const float* __restrict__ Ab,
                                           const float* __restrict__ Bb,
                                           int i0, int i1,
                                           double* __restrict__ out, int j,
                                           float (*sred)[54]) {
    float acc[9*NE];
    #pragma unroll
    for (int k = 0; k < 9*NE; k++) acc[k] = 0.f;

    if (j < NH) {
        const float* __restrict__ A = Ab + i0*PH + j;
        const float* __restrict__ B = Bb + i0*PH + j;
        float wa0[3], wa1[3], na[3];
        float wb0[3], wb1[3], nb[3];
        #pragma unroll
        for (int c = 0; c < 3; c++) { wa0[c] = A[c]; wb0[c] = B[c]; }
        A += PH; B += PH;
        #pragma unroll
        for (int c = 0; c < 3; c++) { wa1[c] = A[c]; wb1[c] = B[c]; }
        A += PH; B += PH;
        #pragma unroll
        for (int c = 0; c < 3; c++) { na[c] = A[c]; nb[c] = B[c]; }
        A += PH; B += PH;

        #pragma unroll 2
        for (int i = i0; i < i1; i++) {
            float a[9] = { wa0[0], wa0[1], wa0[2],
                           wa1[0], wa1[1], wa1[2],
                           na[0],  na[1],  na[2] };
            float b[9] = { wb0[0], wb0[1], wb0[2],
                           wb1[0], wb1[1], wb1[2],
                           nb[0],  nb[1],  nb[2] };
            #pragma unroll
            for (int c = 0; c < 3; c++) { na[c] = A[c]; nb[c] = B[c]; }
            A += PH; B += PH;

            #pragma unroll
            for (int d = 0; d < 9; d++)
                #pragma unroll
                for (int e = 0; e < NE; e++)
                    acc[d*NE + e] += a[d] * b[EL + e];

            #pragma unroll
            for (int c = 0; c < 3; c++) {
                wa0[c] = wa1[c]; wa1[c] = a[6 + c];
                wb0[c] = wb1[c]; wb1[c] = b[6 + c];
            }
        }
    }

    __shared__ float outv[54];
    block_reduce<9*NE>(acc, sred, outv);
    if (threadIdx.x < 9*NE) {
        const int d = threadIdx.x / NE, e = EL + (threadIdx.x % NE);
        atomicAdd(&out[d*9 + e], (double)outv[threadIdx.x]);
    }
}

// ------------------------- kernel 2: all Grams, one launch -----------------
__global__ void __launch_bounds__(192)
k_gram_all() {
    __shared__ float sred[6][54];
    const int nc = blockIdx.x;
    const int z  = blockIdx.z;
    const int j  = threadIdx.x;
    const int i0 = blockIdx.y * ROWCH;
    const int i1 = (i0 + ROWCH < NH) ? (i0 + ROWCH) : NH;
    const size_t base = (size_t)nc * PP;
    double* __restrict__ out = g_gram + (size_t)(nc*3) * 81;

    if (z == 0)      self_body(g_la + base, i0, i1, out, j, sred);
    else if (z == 1) self_body(g_pr + base, i0, i1, out + 81, j, sred);
    else if (z == 2) cross_body<0,5>(g_la + base, g_pr + base, i0, i1, out + 162, j, sred);
    else             cross_body<5,4>(g_la + base, g_pr + base, i0, i1, out + 162, j, sred);
}

// ------------------------- kernel 3: linear algebra + last-block combine ---
__global__ void __launch_bounds__(32)
k_finalize(float* __restrict__ outp) {
    const int nc = blockIdx.x;
    const int d  = threadIdx.x;
    const int dd = (d < 9) ? d : 0;

    const double* __restrict__ G0 = g_gram + (size_t)(nc*3 + 0)*81;
    const double* __restrict__ G1 = g_gram + (size_t)(nc*3 + 1)*81;
    const double* __restrict__ G2 = g_gram + (size_t)(nc*3 + 2)*81;

    const double invM = 1.0 / (double)M_;
    const double sla_d = G0[45 + dd], spr_d = G1[45 + dd];

    float Cr[9], Pr[9], Br[9];
    #pragma unroll
    for (int e = 0; e < 9; e++) {
        const int lo = (dd < e) ? dd : e;
        const int hi = (dd < e) ? e : dd;
        const int tri = lo*9 - (lo*(lo-1))/2 + (hi - lo);
        const double sla_e = G0[45 + e], spr_e = G1[45 + e];
        Cr[e] = (float)(G0[tri] - sla_d*sla_e*invM + ((e == dd) ? ALPHA : 0.0));
        Pr[e] = (float)(G1[tri] - spr_d*spr_e*invM + ((e == dd) ? ALPHA : 0.0));
        Br[e] = (float)(G2[dd*9 + e] - sla_d*spr_e*invM);
    }

    float Lr[9], Dinv[9];
    #pragma unroll
    for (int k = 0; k < 9; k++) {
        const float pkk = __shfl_sync(FULLM, Pr[k], k);
        const float rs  = rsqrtf(fmaxf(pkk, 1e-30f));
        const float ldk = Pr[k] * rs;
        Lr[k]   = ldk;
        Dinv[k] = rs;
        #pragma unroll
        for (int j = 0; j < 9; j++)
            if (j > k) Pr[j] -= ldk * __shfl_sync(FULLM, ldk, j);
    }

    float Wr[9];
    #pragma unroll
    for (int e = 0; e < 9; e++) {
        float s = Br[e];
        #pragma unroll
        for (int k = 0; k < 9; k++)
            if (k < e) s -= Wr[k] * __shfl_sync(FULLM, Lr[k], e);
        Wr[e] = s * Dinv[e];
    }

    #pragma unroll
    for (int e = 0; e < 9; e++) {
        float s = 0.f;
        #pragma unroll
        for (int k = 0; k < 9; k++)
            s += Wr[k] * __shfl_sync(FULLM, Wr[k], e);
        Cr[e] -= s;
    }

    float dprod = 1.f;
    #pragma unroll
    for (int k = 0; k < 9; k++) {
        const float akk = __shfl_sync(FULLM, Cr[k], k);
        const float as  = fmaxf(akk, 1e-30f);
        const float rs  = rsqrtf(as);
        const float lkk = as * rs;
        dprod *= (lkk + 1e-8f);
        const float ldk = Cr[k] * rs;
        #pragma unroll
        for (int j = 0; j < 9; j++)
            if (j > k) Cr[j] -= ldk * __shfl_sync(FULLM, ldk, j);
    }

    // last block through combines and writes the output (saves a launch)
    if (d == 0) {
        atomicAdd(&g_rmi, (double)logf(dprod));
        __threadfence();
        const int prev = atomicAdd(&g_done, 1);
        if (prev == NC - 1) {
            const double rmi_total = g_rmi / (double)(N_ * 9);
            const double bce_loss  = g_bce / (g_valid + 1.0);
            outp[0] = (float)(0.5 * bce_loss + 0.5 * rmi_total);
        }
    }
}

// ------------------------- launch ------------------------------------------
extern "C" void kernel_launch(void* const* d_in, const int* in_sizes, int n_in,
                              void* d_out, int out_size) {
    const float* logits = (const float*)d_in[0];
    const void*  labels = d_in[1];

    k_init<<<(GRAMSZ + 255) / 256, 256>>>(labels);
    dim3 gp(PH, N_);
    k_pool_bce<<<gp, 192>>>(logits, labels);
    dim3 g2(NC, RSPLIT, 4);
    k_gram_all<<<g2, 192>>>();
    k_finalize<<<NC, 32>>>((float*)d_out);
}